// round 12
// baseline (speedup 1.0000x reference)
#include <cuda_runtime.h>
#include <cuda_bf16.h>
#include <cstdint>
#include <math.h>

// ---------------------------------------------------------------------------
// Problem constants
// ---------------------------------------------------------------------------
#define SQ   128            // seq len
#define BB   128            // batch
#define EE   256            // embed dim
#define HH   256            // hidden
#define G4   1024           // 4*H
#define D2   512            // 2*H
#define MBS  (BB*SQ)        // 16384
#define MX   (3*MBS)        // 49152 rows of X
#define OUTREG (BB*SQ*D2)   // 8388608 floats per output tensor

// LSTM-mma geometry (R4 verified)
#define WPAD 260
#define HPAD 260
#define GPAD 132
#define LSTM_SMEM_BYTES ((128*WPAD + 64*HPAD) * 4)   // 199,680 B

// tgemm dynamic smem: 2 buffers x (A + B) x 128*36 words
#define TG_BUF (128 * 36)
#define TGEMM_SMEM_BYTES (4 * TG_BUF * 4)            // 73,728 B

// ---------------------------------------------------------------------------
// Device scratch
// ---------------------------------------------------------------------------
__device__ float g_X    [3*MBS*EE];     //  50 MB  embedded inputs (tf32-rounded)
__device__ float g_XpreF[3*MBS*G4];     // 201 MB  X@Wih_f^T + bias_f  (fp32)
__device__ float g_XpreB[3*MBS*G4];     // 201 MB
__device__ float g_WihFr[G4*EE];        //   1 MB  tf32-rounded Wih_f
__device__ float g_WihBr[G4*EE];        //   1 MB  tf32-rounded Wih_b
__device__ float g_S1Wr [D2*D2];        //   1 MB  tf32-rounded S1_W
__device__ float g_biasf[G4];
__device__ float g_biasb[G4];
__device__ float g_Y    [3*MBS*D2];     // 100 MB  BiLSTM outputs (tf32-rounded)
__device__ float g_Ct   [2*MBS*D2];     //  67 MB  tanh(S1(C)) (tf32-rounded)
__device__ float g_YqT  [MBS*D2];       //  33 MB  transpose of Q stream (rounded)
__device__ float g_MQT  [MBS*D2];       //  33 MB  transpose of MQ (rounded)
__device__ float g_Hm   [BB*SQ*SQ];     // 8.4 MB  logits (fp32)
__device__ float g_AQ   [BB*SQ*SQ];     //          softmax (tf32-rounded)
__device__ float g_AC   [BB*SQ*SQ];
__device__ int   g_flag [128];          // per-(group,gate) progress flags (96 used)

// ---------------------------------------------------------------------------
// tf32 helpers
// ---------------------------------------------------------------------------
__device__ __forceinline__ unsigned f2tf(float f) {
    unsigned r;
    asm("cvt.rna.tf32.f32 %0, %1;" : "=r"(r) : "f"(f));
    return r;
}
__device__ __forceinline__ float rndtf(float f) {     // rna tf32 round, kept in fp32
    return __uint_as_float(f2tf(f));
}
__device__ __forceinline__ void mma_tf32(float* d, const unsigned a[4],
                                         unsigned b0, unsigned b1) {
    asm volatile(
        "mma.sync.aligned.m16n8k8.row.col.f32.tf32.tf32.f32 "
        "{%0,%1,%2,%3},{%4,%5,%6,%7},{%8,%9},{%0,%1,%2,%3};"
        : "+f"(d[0]), "+f"(d[1]), "+f"(d[2]), "+f"(d[3])
        : "r"(a[0]), "r"(a[1]), "r"(a[2]), "r"(a[3]), "r"(b0), "r"(b1));
}
__device__ __forceinline__ unsigned smem_u32(const void* p) {
    unsigned a;
    asm("{ .reg .u64 t; cvta.to.shared.u64 t, %1; cvt.u32.u64 %0, t; }"
        : "=r"(a) : "l"(p));
    return a;
}
__device__ __forceinline__ void prefetchL2(const void* p) {
    asm volatile("prefetch.global.L2 [%0];" :: "l"(p));
}

// ---------------------------------------------------------------------------
// Prep: bias fold, flag reset, tf32-rounded weight copies.
// ---------------------------------------------------------------------------
__global__ void prep_kernel(const float* __restrict__ bihF, const float* __restrict__ bhhF,
                            const float* __restrict__ bihB, const float* __restrict__ bhhB,
                            const float* __restrict__ WihF, const float* __restrict__ WihB,
                            const float* __restrict__ S1W,
                            float* __restrict__ biasf, float* __restrict__ biasb,
                            float* __restrict__ wihFr, float* __restrict__ wihBr,
                            float* __restrict__ s1wr, int* __restrict__ flags)
{
    int gid = blockIdx.x * 256 + threadIdx.x;   // 0..262143
    wihFr[gid] = rndtf(WihF[gid]);
    wihBr[gid] = rndtf(WihB[gid]);
    s1wr [gid] = rndtf(S1W [gid]);
    if (gid < G4) {
        biasf[gid] = bihF[gid] + bhhF[gid];
        biasb[gid] = bihB[gid] + bhhB[gid];
    }
    if (gid < 128) flags[gid] = 0;
}

// ---------------------------------------------------------------------------
// Embedding gather (tf32-rounded output — X is a GEMM operand)
// ---------------------------------------------------------------------------
__global__ void embed_kernel(const int* __restrict__ tq, const int* __restrict__ tc,
                             const int* __restrict__ tc2,
                             const float4* __restrict__ emb, float4* __restrict__ X)
{
    int gid = blockIdx.x * 256 + threadIdx.x;      // 3145728 total
    int c4  = gid & 63;
    int row = gid >> 6;
    int seq = row / MBS;
    int rb  = row - seq * MBS;
    int b   = rb >> 7, s = rb & 127;
    const int* tok = (seq == 0) ? tq : ((seq == 1) ? tc : tc2);
    int t = tok[s * BB + b];
    float4 v = emb[(size_t)t * 64 + c4];
    v.x = rndtf(v.x); v.y = rndtf(v.y); v.z = rndtf(v.z); v.w = rndtf(v.w);
    X[(size_t)row * 64 + c4] = v;
}

// ---------------------------------------------------------------------------
// tf32 tensor-core GEMM, NT form, 2-stage cp.async pipeline (dynamic smem).
// Operands PRE-ROUNDED to tf32 -> raw-bit feed == rna conversion.
// ---------------------------------------------------------------------------
template<int EPI>   // 0=none, 1=+bias[n], 2=rndtf(tanh(x+bias[n]))
__global__ __launch_bounds__(256) void tgemm_kernel(
    int M, int N, int K,
    const float* __restrict__ A, int lda, size_t sA,
    const float* __restrict__ B, int ldb, size_t sB,
    float* __restrict__ C, int ldc, size_t sC,
    const float* __restrict__ bias)
{
    extern __shared__ unsigned tsm[];
    unsigned* As[2] = { tsm,              tsm + TG_BUF };
    unsigned* Bs[2] = { tsm + 2 * TG_BUF, tsm + 3 * TG_BUF };

    int bx = blockIdx.x, by = blockIdx.y, bz = blockIdx.z;
    const float* Ap = A + (size_t)bz * sA + (size_t)by * 128 * lda;
    const float* Bp = B + (size_t)bz * sB + (size_t)bx * 128 * ldb;
    float* Cp = C + (size_t)bz * sC + (size_t)by * 128 * ldc + (size_t)bx * 128;

    int tid = threadIdx.x, lane = tid & 31, warp = tid >> 5;
    int wm = warp & 3, wn = warp >> 2;
    int ly = lane >> 2, lx = lane & 3;

    int cpRow = tid >> 3, cpC4 = (tid & 7) * 4;

    float acc[2][8][4];
#pragma unroll
    for (int im = 0; im < 2; im++)
#pragma unroll
        for (int nt = 0; nt < 8; nt++)
#pragma unroll
            for (int j = 0; j < 4; j++) acc[im][nt][j] = 0.f;

    int NC = K >> 5;

    auto issue = [&](int kc, int b) {
        int k0 = kc * 32;
#pragma unroll
        for (int i = 0; i < 4; i++) {
            int row = cpRow + 32 * i;
            unsigned sa = smem_u32(&As[b][row * 36 + cpC4]);
            asm volatile("cp.async.cg.shared.global [%0], [%1], 16;"
                         :: "r"(sa), "l"(Ap + (size_t)row * lda + k0 + cpC4));
            unsigned sb = smem_u32(&Bs[b][row * 36 + cpC4]);
            asm volatile("cp.async.cg.shared.global [%0], [%1], 16;"
                         :: "r"(sb), "l"(Bp + (size_t)row * ldb + k0 + cpC4));
        }
        asm volatile("cp.async.commit_group;");
    };

    issue(0, 0);
    for (int kc = 0; kc < NC; kc++) {
        int b = kc & 1;
        if (kc + 1 < NC) {
            issue(kc + 1, b ^ 1);
            asm volatile("cp.async.wait_group 1;");
        } else {
            asm volatile("cp.async.wait_group 0;");
        }
        __syncthreads();

        const unsigned* Ab = As[b];
        const unsigned* Bb = Bs[b];
#pragma unroll
        for (int kk = 0; kk < 4; kk++) {
            int k8 = kk * 8;
            unsigned a[2][4];
#pragma unroll
            for (int im = 0; im < 2; im++) {
                int rb = wm * 32 + im * 16;
                a[im][0] = Ab[(rb + ly) * 36 + k8 + lx];
                a[im][1] = Ab[(rb + ly + 8) * 36 + k8 + lx];
                a[im][2] = Ab[(rb + ly) * 36 + k8 + lx + 4];
                a[im][3] = Ab[(rb + ly + 8) * 36 + k8 + lx + 4];
            }
#pragma unroll
            for (int nt = 0; nt < 8; nt++) {
                int n = wn * 64 + nt * 8 + ly;
                unsigned b0 = Bb[n * 36 + k8 + lx];
                unsigned b1 = Bb[n * 36 + k8 + lx + 4];
                mma_tf32(acc[0][nt], a[0], b0, b1);
                mma_tf32(acc[1][nt], a[1], b0, b1);
            }
        }
        __syncthreads();
    }

#pragma unroll
    for (int im = 0; im < 2; im++) {
#pragma unroll
        for (int nt = 0; nt < 8; nt++) {
            int n0 = wn * 64 + nt * 8 + lx * 2;
            int r0 = wm * 32 + im * 16 + ly;
            float2 v0 = make_float2(acc[im][nt][0], acc[im][nt][1]);
            float2 v1 = make_float2(acc[im][nt][2], acc[im][nt][3]);
            if constexpr (EPI >= 1) {
                float b0v = bias[bx * 128 + n0], b1v = bias[bx * 128 + n0 + 1];
                v0.x += b0v; v0.y += b1v; v1.x += b0v; v1.y += b1v;
            }
            if constexpr (EPI == 2) {
                v0.x = rndtf(tanhf(v0.x)); v0.y = rndtf(tanhf(v0.y));
                v1.x = rndtf(tanhf(v1.x)); v1.y = rndtf(tanhf(v1.y));
            }
            *reinterpret_cast<float2*>(&Cp[(size_t)r0 * ldc + n0]) = v0;
            *reinterpret_cast<float2*>(&Cp[(size_t)(r0 + 8) * ldc + n0]) = v1;
        }
    }
}

// ---------------------------------------------------------------------------
// Batched transpose (tf32-rounded output)
// ---------------------------------------------------------------------------
__global__ void transpose_kernel(const float* __restrict__ in, float* __restrict__ out)
{
    __shared__ float tile[32][33];
    int b = blockIdx.z;
    const float* ip = in + (size_t)b * SQ * D2;
    float* op = out + (size_t)b * SQ * D2;
    int c0 = blockIdx.x * 32, r0 = blockIdx.y * 32;
    int x = threadIdx.x, y = threadIdx.y;
#pragma unroll
    for (int j = 0; j < 32; j += 8)
        tile[y + j][x] = ip[(size_t)(r0 + y + j) * D2 + c0 + x];
    __syncthreads();
#pragma unroll
    for (int j = 0; j < 32; j += 8)
        op[(size_t)(c0 + y + j) * SQ + r0 + x] = rndtf(tile[x][y + j]);
}

// ---------------------------------------------------------------------------
// LSTM recurrence — R10 core, exchange on per-producer flags:
//  producer: fence -> sync -> tid0 stores flag[grp][gg] = t+1
//  consumer: warp w spins on flag[grp][w], reloads ONLY chunk w; own chunk
//            from registers. Flags monotonic, Y addresses per-step, all 96
//            CTAs resident -> deadlock-free, max skew 1 step.
// ---------------------------------------------------------------------------
__global__ __launch_bounds__(256) void lstm_mma_kernel(
    const float* __restrict__ xpreF, const float* __restrict__ xpreB,
    const float* __restrict__ WhhF, const float* __restrict__ WhhB,
    const float* __restrict__ h_q, const float* __restrict__ c_q,
    const float* __restrict__ h_c, const float* __restrict__ c_c,
    const float* __restrict__ h_c2, const float* __restrict__ c_c2,
    float* __restrict__ Y, int* __restrict__ flags)
{
    extern __shared__ unsigned sm[];
    unsigned* smW = sm;                  // [128][WPAD] tf32 weights
    unsigned* smH = sm + 128 * WPAD;     // [64][HPAD] tf32 h  (aliased by G)
    float*    smG = (float*)smH;         // [64][GPAD] fp32 gates

    int bx  = blockIdx.x;
    int sd  = bx >> 4;
    int rem = bx & 15;
    int bg  = rem >> 3;
    int gg  = rem & 7;
    int seq = sd >> 1, dir = sd & 1;
    int grp = sd * 2 + bg;

    int tid  = threadIdx.x;
    int lane = tid & 31, warp = tid >> 5;
    int ly = lane >> 2, lx = lane & 3;
    int mt = warp & 3;
    int nh = warp >> 2;

    const float* xpre = (dir ? xpreB : xpreF) + (size_t)seq * MBS * G4;
    const float* Whh  = dir ? WhhB : WhhF;
    const float* h0p  = (seq == 0) ? h_q : ((seq == 1) ? h_c : h_c2);
    const float* c0p  = (seq == 0) ? c_q : ((seq == 1) ? c_c : c_c2);

    for (int i = tid; i < 128 * 256; i += 256) {
        int r = i >> 8, c = i & 255;
        int g = r >> 5, u_ = r & 31;
        smW[r * WPAD + c] = f2tf(Whh[(size_t)(g * 256 + gg * 32 + u_) * 256 + c]);
    }
    for (int i = tid; i < 64 * 64; i += 256) {
        int r = i >> 6, c4 = (i & 63) * 4;
        float4 v = *(const float4*)&h0p[((size_t)(dir * BB + bg * 64 + r)) * HH + c4];
        uint4 w; w.x = f2tf(v.x); w.y = f2tf(v.y); w.z = f2tf(v.z); w.w = f2tf(v.w);
        *(uint4*)&smH[r * HPAD + c4] = w;
    }
    int u  = tid & 31;
    int mb = warp * 8;
    float cst[8];
#pragma unroll
    for (int p = 0; p < 8; p++)
        cst[p] = c0p[((size_t)(dir * BB + bg * 64 + mb + p)) * HH + gg * 32 + u];
    __syncthreads();

    volatile int* fl = (volatile int*)(flags + grp * 8);
    float hv[8];

    for (int t = 0; t < SQ; t++) {
        int te = dir ? (SQ - 1 - t) : t;

        // ---- prefetch this step's xpre values into L2 during MMA ----
#pragma unroll
        for (int p = 0; p < 8; p++) {
            const float* xp = &xpre[(((size_t)(bg * 64 + mb + p)) * SQ + te) * G4 + gg * 32 + u];
            prefetchL2(xp);
            prefetchL2(xp + 256);
            prefetchL2(xp + 512);
            prefetchL2(xp + 768);
        }

        // ---- MMA phase (reads smH) ----
        float acc[8][4];
#pragma unroll
        for (int n = 0; n < 8; n++)
#pragma unroll
            for (int j = 0; j < 4; j++) acc[n][j] = 0.f;

        const unsigned* hA = smH + (mt * 16 + ly) * HPAD + lx;
#pragma unroll 4
        for (int k0 = 0; k0 < 256; k0 += 8) {
            unsigned a[4];
            a[0] = hA[k0];
            a[1] = hA[k0 + 8 * HPAD];
            a[2] = hA[k0 + 4];
            a[3] = hA[k0 + 8 * HPAD + 4];
#pragma unroll
            for (int nt = 0; nt < 8; nt++) {
                const unsigned* wB = smW + (nh * 64 + nt * 8 + ly) * WPAD + k0 + lx;
                mma_tf32(acc[nt], a, wB[0], wB[4]);
            }
        }
        __syncthreads();

#pragma unroll
        for (int nt = 0; nt < 8; nt++) {
            int n0 = nh * 64 + nt * 8 + lx * 2;
            int r0 = mt * 16 + ly;
            *(float2*)&smG[r0 * GPAD + n0]       = make_float2(acc[nt][0], acc[nt][1]);
            *(float2*)&smG[(r0 + 8) * GPAD + n0] = make_float2(acc[nt][2], acc[nt][3]);
        }
        __syncthreads();

#pragma unroll
        for (int p = 0; p < 8; p++) {
            int m = mb + p;
            const float* xp = &xpre[(((size_t)(bg * 64 + m)) * SQ + te) * G4 + gg * 32 + u];
            float gi = smG[m * GPAD +      u] + xp[0];
            float gf = smG[m * GPAD + 32 + u] + xp[256];
            float gc = smG[m * GPAD + 64 + u] + xp[512];
            float go = smG[m * GPAD + 96 + u] + xp[768];
            float i_ = 1.f / (1.f + __expf(-gi));
            float f_ = 1.f / (1.f + __expf(-gf));
            float g_ = tanhf(gc);
            float o_ = 1.f / (1.f + __expf(-go));
            float c  = f_ * cst[p] + i_ * g_;
            cst[p] = c;
            float h = rndtf(o_ * tanhf(c));
            hv[p] = h;
            Y[(((size_t)(seq * BB + bg * 64 + m)) * SQ + te) * D2 + dir * HH + gg * 32 + u] = h;
        }

        // ---- release: my chunk of h (in Y) is globally visible ----
        __threadfence();
        __syncthreads();
        if (tid == 0) fl[gg] = t + 1;

        // ---- own chunk into smH from registers (no global roundtrip) ----
#pragma unroll
        for (int p = 0; p < 8; p++)
            smH[(mb + p) * HPAD + gg * 32 + u] = f2tf(hv[p]);

        // ---- warp w consumes chunk w as soon as its producer signals ----
        if (warp != gg) {
            while (fl[warp] < t + 1) { }
            int cb = dir * HH + warp * 32;
            size_t rowBase = (((size_t)(seq * BB + bg * 64)) * SQ + te) * D2;
#pragma unroll
            for (int ii = 0; ii < 16; ii++) {
                int i = lane + 32 * ii;
                int r = i >> 3, c4 = (i & 7) * 4;
                float4 v = __ldcg((const float4*)&Y[rowBase + (size_t)r * SQ * D2 + cb + c4]);
                uint4 w; w.x = f2tf(v.x); w.y = f2tf(v.y); w.z = f2tf(v.z); w.w = f2tf(v.w);
                *(uint4*)&smH[r * HPAD + warp * 32 + c4] = w;
            }
        }
        __syncthreads();
    }
}

// ---------------------------------------------------------------------------
// Softmax kernels (tf32-rounded outputs)
// ---------------------------------------------------------------------------
__global__ void row_softmax(const float* __restrict__ Hm, float* __restrict__ AQ)
{
    int warp = (blockIdx.x * blockDim.x + threadIdx.x) >> 5;
    int lane = threadIdx.x & 31;
    const float* base = Hm + (size_t)warp * SQ;
    float v[4], m = -1e30f;
#pragma unroll
    for (int u = 0; u < 4; u++) { v[u] = base[lane + 32 * u]; m = fmaxf(m, v[u]); }
#pragma unroll
    for (int o = 16; o > 0; o >>= 1) m = fmaxf(m, __shfl_xor_sync(0xffffffffu, m, o));
    float s = 0.f;
#pragma unroll
    for (int u = 0; u < 4; u++) { v[u] = __expf(v[u] - m); s += v[u]; }
#pragma unroll
    for (int o = 16; o > 0; o >>= 1) s += __shfl_xor_sync(0xffffffffu, s, o);
    float inv = 1.f / s;
    float* out = AQ + (size_t)warp * SQ;
#pragma unroll
    for (int u = 0; u < 4; u++) out[lane + 32 * u] = rndtf(v[u] * inv);
}

__global__ void col_softmax(const float* __restrict__ Hm, float* __restrict__ AC)
{
    int warp = (blockIdx.x * blockDim.x + threadIdx.x) >> 5;
    int lane = threadIdx.x & 31;
    int b = warp >> 7, s = warp & 127;
    const float* base = Hm + (size_t)b * SQ * SQ + s;
    float v[4], m = -1e30f;
#pragma unroll
    for (int u = 0; u < 4; u++) { v[u] = base[(size_t)(lane + 32 * u) * SQ]; m = fmaxf(m, v[u]); }
#pragma unroll
    for (int o = 16; o > 0; o >>= 1) m = fmaxf(m, __shfl_xor_sync(0xffffffffu, m, o));
    float sm = 0.f;
#pragma unroll
    for (int u = 0; u < 4; u++) { v[u] = __expf(v[u] - m); sm += v[u]; }
#pragma unroll
    for (int o = 16; o > 0; o >>= 1) sm += __shfl_xor_sync(0xffffffffu, sm, o);
    float inv = 1.f / sm;
    float* out = AC + (size_t)b * SQ * SQ + (size_t)s * SQ;
#pragma unroll
    for (int u = 0; u < 4; u++) out[lane + 32 * u] = rndtf(v[u] * inv);
}

// ---------------------------------------------------------------------------
// Host-side GEMM dispatch (dynamic smem)
// ---------------------------------------------------------------------------
static void run_tgemm(int epi, int M, int N, int K,
                      const float* A, int lda, size_t sA,
                      const float* B, int ldb, size_t sB,
                      float* C, int ldc, size_t sC,
                      const float* bias, int batch)
{
    dim3 grid(N / 128, M / 128, batch), block(256);
    size_t sh = TGEMM_SMEM_BYTES;
    if (epi == 0)      tgemm_kernel<0><<<grid, block, sh>>>(M, N, K, A, lda, sA, B, ldb, sB, C, ldc, sC, bias);
    else if (epi == 1) tgemm_kernel<1><<<grid, block, sh>>>(M, N, K, A, lda, sA, B, ldb, sB, C, ldc, sC, bias);
    else               tgemm_kernel<2><<<grid, block, sh>>>(M, N, K, A, lda, sA, B, ldb, sB, C, ldc, sC, bias);
}

// ---------------------------------------------------------------------------
// kernel_launch
// ---------------------------------------------------------------------------
extern "C" void kernel_launch(void* const* d_in, const int* in_sizes, int n_in,
                              void* d_out, int out_size)
{
    (void)in_sizes; (void)n_in; (void)out_size;
    const int*   inQ   = (const int*)d_in[1];
    const int*   inC   = (const int*)d_in[2];
    const int*   inC2  = (const int*)d_in[3];
    const float* hidQ  = (const float*)d_in[4];
    const float* celQ  = (const float*)d_in[5];
    const float* hidC  = (const float*)d_in[6];
    const float* celC  = (const float*)d_in[7];
    const float* hidC2 = (const float*)d_in[8];
    const float* celC2 = (const float*)d_in[9];
    const float* emb   = (const float*)d_in[10];
    const float* WihF  = (const float*)d_in[11];
    const float* WhhF  = (const float*)d_in[12];
    const float* bihF  = (const float*)d_in[13];
    const float* bhhF  = (const float*)d_in[14];
    const float* WihB  = (const float*)d_in[15];
    const float* WhhB  = (const float*)d_in[16];
    const float* bihB  = (const float*)d_in[17];
    const float* bhhB  = (const float*)d_in[18];
    const float* S1W   = (const float*)d_in[19];
    const float* S1b   = (const float*)d_in[20];
    float* out = (float*)d_out;

    void *pX, *pXpF, *pXpB, *pWFr, *pWBr, *pS1r, *pBf, *pBb, *pY, *pCt,
         *pYqT, *pMQT, *pHm, *pAQ, *pAC, *pFlag;
    cudaGetSymbolAddress(&pX,   g_X);
    cudaGetSymbolAddress(&pXpF, g_XpreF);
    cudaGetSymbolAddress(&pXpB, g_XpreB);
    cudaGetSymbolAddress(&pWFr, g_WihFr);
    cudaGetSymbolAddress(&pWBr, g_WihBr);
    cudaGetSymbolAddress(&pS1r, g_S1Wr);
    cudaGetSymbolAddress(&pBf,  g_biasf);
    cudaGetSymbolAddress(&pBb,  g_biasb);
    cudaGetSymbolAddress(&pY,   g_Y);
    cudaGetSymbolAddress(&pCt,  g_Ct);
    cudaGetSymbolAddress(&pYqT, g_YqT);
    cudaGetSymbolAddress(&pMQT, g_MQT);
    cudaGetSymbolAddress(&pHm,  g_Hm);
    cudaGetSymbolAddress(&pAQ,  g_AQ);
    cudaGetSymbolAddress(&pAC,  g_AC);
    cudaGetSymbolAddress(&pFlag, g_flag);
    float* X    = (float*)pX;
    float* XpF  = (float*)pXpF;
    float* XpB  = (float*)pXpB;
    float* WFr  = (float*)pWFr;
    float* WBr  = (float*)pWBr;
    float* S1r  = (float*)pS1r;
    float* Bf   = (float*)pBf;
    float* Bb   = (float*)pBb;
    float* Y    = (float*)pY;
    float* Ct   = (float*)pCt;
    float* YqT  = (float*)pYqT;
    float* MQT  = (float*)pMQT;
    float* Hm   = (float*)pHm;
    float* AQ   = (float*)pAQ;
    float* AC   = (float*)pAC;
    int*   flags = (int*)pFlag;

    cudaFuncSetAttribute(lstm_mma_kernel,
                         cudaFuncAttributeMaxDynamicSharedMemorySize,
                         LSTM_SMEM_BYTES);
    cudaFuncSetAttribute(tgemm_kernel<0>,
                         cudaFuncAttributeMaxDynamicSharedMemorySize,
                         TGEMM_SMEM_BYTES);
    cudaFuncSetAttribute(tgemm_kernel<1>,
                         cudaFuncAttributeMaxDynamicSharedMemorySize,
                         TGEMM_SMEM_BYTES);
    cudaFuncSetAttribute(tgemm_kernel<2>,
                         cudaFuncAttributeMaxDynamicSharedMemorySize,
                         TGEMM_SMEM_BYTES);

    // 1. prep: bias fold, flag reset, rounded weight copies
    prep_kernel<<<1024, 256>>>(bihF, bhhF, bihB, bhhB, WihF, WihB, S1W,
                               Bf, Bb, WFr, WBr, S1r, flags);

    // 2. embedding gather (rounded)
    embed_kernel<<<12288, 256>>>(inQ, inC, inC2, (const float4*)emb, (float4*)X);

    // 3. input GEMMs: Xpre = X @ Wih^T + (bih+bhh)
    run_tgemm(1, MX, G4, EE, X, EE, 0, WFr, EE, 0, XpF, G4, 0, Bf, 1);
    run_tgemm(1, MX, G4, EE, X, EE, 0, WBr, EE, 0, XpB, G4, 0, Bb, 1);

    // 4. recurrence (tensor-core, 96 resident CTAs, per-producer-flag exchange)
    lstm_mma_kernel<<<96, 256, LSTM_SMEM_BYTES>>>(
        XpF, XpB, WhhF, WhhB,
        hidQ, celQ, hidC, celC, hidC2, celC2, Y, flags);

    // 5. Ct = rndtf(tanh(Y_c @ S1_W^T + S1_b))
    run_tgemm(2, MBS, D2, D2, Y + (size_t)1 * MBS * D2, D2, 0,
              S1r, D2, 0, Ct, D2, 0, S1b, 1);
    run_tgemm(2, MBS, D2, D2, Y + (size_t)2 * MBS * D2, D2, 0,
              S1r, D2, 0, Ct + (size_t)MBS * D2, D2, 0, S1b, 1);

    // 5b. Yq^T for the MQ GEMM's B operand
    {
        dim3 tg(D2 / 32, SQ / 32, BB), tb(32, 8);
        transpose_kernel<<<tg, tb>>>(Y, YqT);
    }

    // 6. attention for pairs (Q,C) and (Q,C2)
    for (int p = 0; p < 2; p++) {
        run_tgemm(0, SQ, SQ, D2,
                  Y, D2, (size_t)SQ * D2,
                  Ct + (size_t)p * MBS * D2, D2, (size_t)SQ * D2,
                  Hm, SQ, (size_t)SQ * SQ, nullptr, BB);
        row_softmax<<<2048, 256>>>(Hm, AQ);
        col_softmax<<<2048, 256>>>(Hm, AC);
        float* outMQ = out + (size_t)(2 * p) * OUTREG;
        float* outMC = out + (size_t)(2 * p + 1) * OUTREG;
        run_tgemm(0, SQ, D2, SQ,
                  AQ, SQ, (size_t)SQ * SQ,
                  YqT, SQ, (size_t)SQ * D2,
                  outMQ, D2, (size_t)SQ * D2, nullptr, BB);
        {
            dim3 tg(D2 / 32, SQ / 32, BB), tb(32, 8);
            transpose_kernel<<<tg, tb>>>(outMQ, MQT);
        }
        run_tgemm(0, SQ, D2, SQ,
                  AC, SQ, (size_t)SQ * SQ,
                  MQT, SQ, (size_t)SQ * D2,
                  outMC, D2, (size_t)SQ * D2, nullptr, BB);
    }
}

// round 14
// speedup vs baseline: 1.1549x; 1.1549x over previous
#include <cuda_runtime.h>
#include <cuda_fp16.h>
#include <cstdint>
#include <math.h>

// ---------------------------------------------------------------------------
// Problem constants
// ---------------------------------------------------------------------------
#define SQ   128            // seq len
#define BB   128            // batch
#define EE   256            // embed dim
#define HH   256            // hidden
#define G4   1024           // 4*H
#define D2   512            // 2*H
#define MBS  (BB*SQ)        // 16384
#define MX   (3*MBS)        // 49152 rows of X
#define OUTREG (BB*SQ*D2)   // 8388608 floats per output tensor

// LSTM-mma geometry (R4/R10 verified)
#define WPAD 260
#define HPAD 260
#define GPAD 132
#define LSTM_SMEM_BYTES ((128*WPAD + 64*HPAD) * 4)   // 199,680 B

// fp16 tgemm smem geometry: 16 half2 words per 32-half k-chunk, pad to 20
#define TGW 20
#define TGH_BUF (128 * TGW)    // words per matrix per buffer

// ---------------------------------------------------------------------------
// Device scratch
// ---------------------------------------------------------------------------
__device__ __half g_Xh  [3*MBS*EE];     //  25 MB  embedded inputs (fp16)
__device__ float  g_XpreF[3*MBS*G4];    // 201 MB  X@Wih_f^T + bias_f (fp32)
__device__ float  g_XpreB[3*MBS*G4];    // 201 MB
__device__ __half g_WihFh[G4*EE];       // 0.5 MB  fp16 Wih_f
__device__ __half g_WihBh[G4*EE];       // 0.5 MB  fp16 Wih_b
__device__ __half g_S1Wh [D2*D2];       // 0.5 MB  fp16 S1_W
__device__ float  g_biasf[G4];
__device__ float  g_biasb[G4];
__device__ float  g_Y    [3*MBS*D2];    // 100 MB  BiLSTM outputs (tf32-rounded fp32)
__device__ __half g_Yh   [3*MBS*D2];    //  50 MB  fp16 copy of Y (GEMM operand)
__device__ __half g_Ct   [2*MBS*D2];    //  34 MB  tanh(S1(C)) (fp16)
__device__ __half g_YqT  [MBS*D2];      //  17 MB  transpose of Q stream (fp16)
__device__ __half g_MQT  [MBS*D2];      //  17 MB  transpose of MQ (fp16)
__device__ float  g_Hm   [BB*SQ*SQ];    // 8.4 MB  logits (fp32)
__device__ __half g_AQ   [BB*SQ*SQ];    //          softmax (fp16)
__device__ __half g_AC   [BB*SQ*SQ];
__device__ int    g_bar  [12];          // barrier counters (6 streams x 2 halves)

// ---------------------------------------------------------------------------
// helpers
// ---------------------------------------------------------------------------
__device__ __forceinline__ unsigned f2tf(float f) {
    unsigned r;
    asm("cvt.rna.tf32.f32 %0, %1;" : "=r"(r) : "f"(f));
    return r;
}
__device__ __forceinline__ float rndtf(float f) {
    return __uint_as_float(f2tf(f));
}
__device__ __forceinline__ void mma_tf32(float* d, const unsigned a[4],
                                         unsigned b0, unsigned b1) {
    asm volatile(
        "mma.sync.aligned.m16n8k8.row.col.f32.tf32.tf32.f32 "
        "{%0,%1,%2,%3},{%4,%5,%6,%7},{%8,%9},{%0,%1,%2,%3};"
        : "+f"(d[0]), "+f"(d[1]), "+f"(d[2]), "+f"(d[3])
        : "r"(a[0]), "r"(a[1]), "r"(a[2]), "r"(a[3]), "r"(b0), "r"(b1));
}
__device__ __forceinline__ void mma_f16(float* d, const unsigned a[4],
                                        unsigned b0, unsigned b1) {
    asm volatile(
        "mma.sync.aligned.m16n8k16.row.col.f32.f16.f16.f32 "
        "{%0,%1,%2,%3},{%4,%5,%6,%7},{%8,%9},{%0,%1,%2,%3};"
        : "+f"(d[0]), "+f"(d[1]), "+f"(d[2]), "+f"(d[3])
        : "r"(a[0]), "r"(a[1]), "r"(a[2]), "r"(a[3]), "r"(b0), "r"(b1));
}
__device__ __forceinline__ unsigned smem_u32(const void* p) {
    unsigned a;
    asm("{ .reg .u64 t; cvta.to.shared.u64 t, %1; cvt.u32.u64 %0, t; }"
        : "=r"(a) : "l"(p));
    return a;
}
__device__ __forceinline__ void prefetchL2(const void* p) {
    asm volatile("prefetch.global.L2 [%0];" :: "l"(p));
}

// ---------------------------------------------------------------------------
// Prep: bias fold, barrier reset, fp16 weight copies
// ---------------------------------------------------------------------------
__global__ void prep_kernel(const float* __restrict__ bihF, const float* __restrict__ bhhF,
                            const float* __restrict__ bihB, const float* __restrict__ bhhB,
                            const float* __restrict__ WihF, const float* __restrict__ WihB,
                            const float* __restrict__ S1W,
                            float* __restrict__ biasf, float* __restrict__ biasb,
                            __half* __restrict__ wihFh, __half* __restrict__ wihBh,
                            __half* __restrict__ s1wh, int* __restrict__ bars)
{
    int gid = blockIdx.x * 256 + threadIdx.x;   // 0..262143
    wihFh[gid] = __float2half_rn(WihF[gid]);
    wihBh[gid] = __float2half_rn(WihB[gid]);
    s1wh [gid] = __float2half_rn(S1W [gid]);
    if (gid < G4) {
        biasf[gid] = bihF[gid] + bhhF[gid];
        biasb[gid] = bihB[gid] + bhhB[gid];
    }
    if (gid < 12) bars[gid] = 0;
}

// ---------------------------------------------------------------------------
// Embedding gather -> fp16 X
// ---------------------------------------------------------------------------
__global__ void embed_kernel(const int* __restrict__ tq, const int* __restrict__ tc,
                             const int* __restrict__ tc2,
                             const float4* __restrict__ emb, __half* __restrict__ Xh)
{
    int gid = blockIdx.x * 256 + threadIdx.x;      // 3145728 total
    int c4  = gid & 63;
    int row = gid >> 6;
    int seq = row / MBS;
    int rb  = row - seq * MBS;
    int b   = rb >> 7, s = rb & 127;
    const int* tok = (seq == 0) ? tq : ((seq == 1) ? tc : tc2);
    int t = tok[s * BB + b];
    float4 v = emb[(size_t)t * 64 + c4];
    __half* dst = Xh + (size_t)row * EE + c4 * 4;
    *(__half2*)(dst)     = __floats2half2_rn(v.x, v.y);
    *(__half2*)(dst + 2) = __floats2half2_rn(v.z, v.w);
}

// ---------------------------------------------------------------------------
// fp32 -> fp16 convert (Y -> Yh)
// ---------------------------------------------------------------------------
__global__ void f2h_kernel(const float4* __restrict__ in, __half2* __restrict__ out)
{
    int gid = blockIdx.x * 256 + threadIdx.x;      // 6291456 float4s
    float4 v = in[gid];
    out[2 * gid]     = __floats2half2_rn(v.x, v.y);
    out[2 * gid + 1] = __floats2half2_rn(v.z, v.w);
}

// ---------------------------------------------------------------------------
// fp16 tensor-core GEMM, NT form:  C = A[M,K] * B[N,K]^T  (+bias)(+tanh->half)
// mma.sync m16n8k16 f16 (fp32 accum). 2-stage cp.async. Tile 128x128,
// K-chunk 32 halves (2 x k16). smem: half2 words, row stride TGW=20
// (fragment reads bank-conflict-free). Same warp layout as verified tf32 GEMM.
// EPI: 0 -> C fp32; 1 -> C fp32 + bias; 2 -> C __half = tanh(x+bias)
// Requires M%128==0, N%128==0, K%32==0.
// ---------------------------------------------------------------------------
template<int EPI>
__global__ __launch_bounds__(256) void tgemm16_kernel(
    int M, int N, int K,
    const __half* __restrict__ A, int lda, size_t sA,
    const __half* __restrict__ B, int ldb, size_t sB,
    void* __restrict__ Cv, int ldc, size_t sC,
    const float* __restrict__ bias)
{
    __shared__ unsigned As[2][TGH_BUF];
    __shared__ unsigned Bs[2][TGH_BUF];

    int bx = blockIdx.x, by = blockIdx.y, bz = blockIdx.z;
    const __half* Ap = A + (size_t)bz * sA + (size_t)by * 128 * lda;
    const __half* Bp = B + (size_t)bz * sB + (size_t)bx * 128 * ldb;

    int tid = threadIdx.x, lane = tid & 31, warp = tid >> 5;
    int wm = warp & 3, wn = warp >> 2;
    int ly = lane >> 2, lx = lane & 3;

    float acc[2][8][4];
#pragma unroll
    for (int im = 0; im < 2; im++)
#pragma unroll
        for (int nt = 0; nt < 8; nt++)
#pragma unroll
            for (int j = 0; j < 4; j++) acc[im][nt][j] = 0.f;

    int NC = K >> 5;   // chunks of 32 halves

    auto issue = [&](int kc, int b) {
        int k0 = kc * 32;                  // half index
#pragma unroll
        for (int i = 0; i < 2; i++) {
            int seg = tid + 256 * i;       // 0..511
            int row = seg >> 2, s4 = (seg & 3) * 4;   // word offset
            unsigned sa = smem_u32(&As[b][row * TGW + s4]);
            asm volatile("cp.async.cg.shared.global [%0], [%1], 16;"
                         :: "r"(sa), "l"(Ap + (size_t)row * lda + k0 + s4 * 2));
            unsigned sb = smem_u32(&Bs[b][row * TGW + s4]);
            asm volatile("cp.async.cg.shared.global [%0], [%1], 16;"
                         :: "r"(sb), "l"(Bp + (size_t)row * ldb + k0 + s4 * 2));
        }
        asm volatile("cp.async.commit_group;");
    };

    issue(0, 0);
    for (int kc = 0; kc < NC; kc++) {
        int b = kc & 1;
        if (kc + 1 < NC) {
            issue(kc + 1, b ^ 1);
            asm volatile("cp.async.wait_group 1;");
        } else {
            asm volatile("cp.async.wait_group 0;");
        }
        __syncthreads();

        const unsigned* Ab = As[b];
        const unsigned* Bb = Bs[b];
#pragma unroll
        for (int kk = 0; kk < 2; kk++) {     // 2 x k16
            int k8w = kk * 8;
            unsigned a[2][4];
#pragma unroll
            for (int im = 0; im < 2; im++) {
                int rb = wm * 32 + im * 16;
                a[im][0] = Ab[(rb + ly) * TGW + k8w + lx];
                a[im][1] = Ab[(rb + ly + 8) * TGW + k8w + lx];
                a[im][2] = Ab[(rb + ly) * TGW + k8w + lx + 4];
                a[im][3] = Ab[(rb + ly + 8) * TGW + k8w + lx + 4];
            }
#pragma unroll
            for (int nt = 0; nt < 8; nt++) {
                int n = wn * 64 + nt * 8 + ly;
                unsigned b0 = Bb[n * TGW + k8w + lx];
                unsigned b1 = Bb[n * TGW + k8w + lx + 4];
                mma_f16(acc[0][nt], a[0], b0, b1);
                mma_f16(acc[1][nt], a[1], b0, b1);
            }
        }
        __syncthreads();
    }

#pragma unroll
    for (int im = 0; im < 2; im++) {
#pragma unroll
        for (int nt = 0; nt < 8; nt++) {
            int n0 = wn * 64 + nt * 8 + lx * 2;
            int r0 = wm * 32 + im * 16 + ly;
            float2 v0 = make_float2(acc[im][nt][0], acc[im][nt][1]);
            float2 v1 = make_float2(acc[im][nt][2], acc[im][nt][3]);
            if constexpr (EPI >= 1) {
                float b0v = bias[bx * 128 + n0], b1v = bias[bx * 128 + n0 + 1];
                v0.x += b0v; v0.y += b1v; v1.x += b0v; v1.y += b1v;
            }
            if constexpr (EPI == 2) {
                __half* Ch = (__half*)Cv + (size_t)bz * sC
                           + (size_t)by * 128 * ldc + (size_t)bx * 128;
                *(__half2*)&Ch[(size_t)r0 * ldc + n0] =
                    __floats2half2_rn(tanhf(v0.x), tanhf(v0.y));
                *(__half2*)&Ch[(size_t)(r0 + 8) * ldc + n0] =
                    __floats2half2_rn(tanhf(v1.x), tanhf(v1.y));
            } else {
                float* Cp = (float*)Cv + (size_t)bz * sC
                          + (size_t)by * 128 * ldc + (size_t)bx * 128;
                *reinterpret_cast<float2*>(&Cp[(size_t)r0 * ldc + n0]) = v0;
                *reinterpret_cast<float2*>(&Cp[(size_t)(r0 + 8) * ldc + n0]) = v1;
            }
        }
    }
}

// ---------------------------------------------------------------------------
// Batched transpose: fp32 in -> fp16 out (GEMM B operands)
// ---------------------------------------------------------------------------
__global__ void transpose_kernel(const float* __restrict__ in, __half* __restrict__ out)
{
    __shared__ float tile[32][33];
    int b = blockIdx.z;
    const float* ip = in + (size_t)b * SQ * D2;
    __half* op = out + (size_t)b * SQ * D2;
    int c0 = blockIdx.x * 32, r0 = blockIdx.y * 32;
    int x = threadIdx.x, y = threadIdx.y;
#pragma unroll
    for (int j = 0; j < 32; j += 8)
        tile[y + j][x] = ip[(size_t)(r0 + y + j) * D2 + c0 + x];
    __syncthreads();
#pragma unroll
    for (int j = 0; j < 32; j += 8)
        op[(size_t)(c0 + y + j) * SQ + r0 + x] = __float2half_rn(tile[x][y + j]);
}

// ---------------------------------------------------------------------------
// LSTM recurrence — R10 verified version (aggregate-barrier exchange),
// with identity-cvt stripping only: Y is written tf32-pre-rounded, so the
// reload/self-store conversions are bit-copies.
// ---------------------------------------------------------------------------
__global__ __launch_bounds__(256) void lstm_mma_kernel(
    const float* __restrict__ xpreF, const float* __restrict__ xpreB,
    const float* __restrict__ WhhF, const float* __restrict__ WhhB,
    const float* __restrict__ h_q, const float* __restrict__ c_q,
    const float* __restrict__ h_c, const float* __restrict__ c_c,
    const float* __restrict__ h_c2, const float* __restrict__ c_c2,
    float* __restrict__ Y, int* __restrict__ bars)
{
    extern __shared__ unsigned sm[];
    unsigned* smW = sm;                  // [128][WPAD] tf32 weights
    unsigned* smH = sm + 128 * WPAD;     // [64][HPAD] tf32 h  (aliased by G)
    float*    smG = (float*)smH;         // [64][GPAD] fp32 gates

    int bx  = blockIdx.x;
    int sd  = bx >> 4;
    int rem = bx & 15;
    int bg  = rem >> 3;
    int gg  = rem & 7;
    int seq = sd >> 1, dir = sd & 1;
    int grp = sd * 2 + bg;

    int tid  = threadIdx.x;
    int lane = tid & 31, warp = tid >> 5;
    int ly = lane >> 2, lx = lane & 3;
    int mt = warp & 3;
    int nh = warp >> 2;

    const float* xpre = (dir ? xpreB : xpreF) + (size_t)seq * MBS * G4;
    const float* Whh  = dir ? WhhB : WhhF;
    const float* h0p  = (seq == 0) ? h_q : ((seq == 1) ? h_c : h_c2);
    const float* c0p  = (seq == 0) ? c_q : ((seq == 1) ? c_c : c_c2);

    for (int i = tid; i < 128 * 256; i += 256) {
        int r = i >> 8, c = i & 255;
        int g = r >> 5, u_ = r & 31;
        smW[r * WPAD + c] = f2tf(Whh[(size_t)(g * 256 + gg * 32 + u_) * 256 + c]);
    }
    for (int i = tid; i < 64 * 64; i += 256) {
        int r = i >> 6, c4 = (i & 63) * 4;
        float4 v = *(const float4*)&h0p[((size_t)(dir * BB + bg * 64 + r)) * HH + c4];
        uint4 w; w.x = f2tf(v.x); w.y = f2tf(v.y); w.z = f2tf(v.z); w.w = f2tf(v.w);
        *(uint4*)&smH[r * HPAD + c4] = w;
    }
    int u  = tid & 31;
    int mb = warp * 8;
    float cst[8];
#pragma unroll
    for (int p = 0; p < 8; p++)
        cst[p] = c0p[((size_t)(dir * BB + bg * 64 + mb + p)) * HH + gg * 32 + u];
    __syncthreads();

    volatile int* vb = (volatile int*)(bars + grp);
    float hv[8];

    for (int t = 0; t < SQ; t++) {
        int te = dir ? (SQ - 1 - t) : t;

        // ---- prefetch this step's xpre values into L2 during MMA ----
#pragma unroll
        for (int p = 0; p < 8; p++) {
            const float* xp = &xpre[(((size_t)(bg * 64 + mb + p)) * SQ + te) * G4 + gg * 32 + u];
            prefetchL2(xp);
            prefetchL2(xp + 256);
            prefetchL2(xp + 512);
            prefetchL2(xp + 768);
        }

        // ---- MMA phase ----
        float acc[8][4];
#pragma unroll
        for (int n = 0; n < 8; n++)
#pragma unroll
            for (int j = 0; j < 4; j++) acc[n][j] = 0.f;

        const unsigned* hA = smH + (mt * 16 + ly) * HPAD + lx;
#pragma unroll 4
        for (int k0 = 0; k0 < 256; k0 += 8) {
            unsigned a[4];
            a[0] = hA[k0];
            a[1] = hA[k0 + 8 * HPAD];
            a[2] = hA[k0 + 4];
            a[3] = hA[k0 + 8 * HPAD + 4];
#pragma unroll
            for (int nt = 0; nt < 8; nt++) {
                const unsigned* wB = smW + (nh * 64 + nt * 8 + ly) * WPAD + k0 + lx;
                mma_tf32(acc[nt], a, wB[0], wB[4]);
            }
        }
        __syncthreads();

#pragma unroll
        for (int nt = 0; nt < 8; nt++) {
            int n0 = nh * 64 + nt * 8 + lx * 2;
            int r0 = mt * 16 + ly;
            *(float2*)&smG[r0 * GPAD + n0]       = make_float2(acc[nt][0], acc[nt][1]);
            *(float2*)&smG[(r0 + 8) * GPAD + n0] = make_float2(acc[nt][2], acc[nt][3]);
        }
        __syncthreads();

#pragma unroll
        for (int p = 0; p < 8; p++) {
            int m = mb + p;
            const float* xp = &xpre[(((size_t)(bg * 64 + m)) * SQ + te) * G4 + gg * 32 + u];
            float gi = smG[m * GPAD +      u] + xp[0];
            float gf = smG[m * GPAD + 32 + u] + xp[256];
            float gc = smG[m * GPAD + 64 + u] + xp[512];
            float go = smG[m * GPAD + 96 + u] + xp[768];
            float i_ = 1.f / (1.f + __expf(-gi));
            float f_ = 1.f / (1.f + __expf(-gf));
            float g_ = tanhf(gc);
            float o_ = 1.f / (1.f + __expf(-go));
            float c  = f_ * cst[p] + i_ * g_;
            cst[p] = c;
            float h = rndtf(o_ * tanhf(c));
            hv[p] = h;
            Y[(((size_t)(seq * BB + bg * 64 + m)) * SQ + te) * D2 + dir * HH + gg * 32 + u] = h;
        }

        __threadfence();
        __syncthreads();
        if (tid == 0) {
            atomicAdd(bars + grp, 1);
            int target = 8 * (t + 1);
            while (*vb < target) { }
            __threadfence();
        }
        __syncthreads();

        // ---- own chunk from registers (already rounded: bit-copy) ----
#pragma unroll
        for (int p = 0; p < 8; p++)
            smH[(mb + p) * HPAD + gg * 32 + u] = __float_as_uint(hv[p]);
        // ---- reload the other 7 chunks (Y pre-rounded: bit-copy) ----
        for (int i = tid; i < 64 * 64; i += 256) {
            if (((i & 63) >> 3) == gg) continue;
            int r = i >> 6, c4 = (i & 63) * 4;
            float4 v = __ldcg((const float4*)&Y[
                (((size_t)(seq * BB + bg * 64 + r)) * SQ + te) * D2 + dir * HH + c4]);
            uint4 w;
            w.x = __float_as_uint(v.x); w.y = __float_as_uint(v.y);
            w.z = __float_as_uint(v.z); w.w = __float_as_uint(v.w);
            *(uint4*)&smH[r * HPAD + c4] = w;
        }
        __syncthreads();
    }
}

// ---------------------------------------------------------------------------
// Softmax kernels (fp16 outputs — GEMM A operands)
// ---------------------------------------------------------------------------
__global__ void row_softmax(const float* __restrict__ Hm, __half* __restrict__ AQ)
{
    int warp = (blockIdx.x * blockDim.x + threadIdx.x) >> 5;
    int lane = threadIdx.x & 31;
    const float* base = Hm + (size_t)warp * SQ;
    float v[4], m = -1e30f;
#pragma unroll
    for (int u = 0; u < 4; u++) { v[u] = base[lane + 32 * u]; m = fmaxf(m, v[u]); }
#pragma unroll
    for (int o = 16; o > 0; o >>= 1) m = fmaxf(m, __shfl_xor_sync(0xffffffffu, m, o));
    float s = 0.f;
#pragma unroll
    for (int u = 0; u < 4; u++) { v[u] = __expf(v[u] - m); s += v[u]; }
#pragma unroll
    for (int o = 16; o > 0; o >>= 1) s += __shfl_xor_sync(0xffffffffu, s, o);
    float inv = 1.f / s;
    __half* out = AQ + (size_t)warp * SQ;
#pragma unroll
    for (int u = 0; u < 4; u++) out[lane + 32 * u] = __float2half_rn(v[u] * inv);
}

__global__ void col_softmax(const float* __restrict__ Hm, __half* __restrict__ AC)
{
    int warp = (blockIdx.x * blockDim.x + threadIdx.x) >> 5;
    int lane = threadIdx.x & 31;
    int b = warp >> 7, s = warp & 127;
    const float* base = Hm + (size_t)b * SQ * SQ + s;
    float v[4], m = -1e30f;
#pragma unroll
    for (int u = 0; u < 4; u++) { v[u] = base[(size_t)(lane + 32 * u) * SQ]; m = fmaxf(m, v[u]); }
#pragma unroll
    for (int o = 16; o > 0; o >>= 1) m = fmaxf(m, __shfl_xor_sync(0xffffffffu, m, o));
    float sm = 0.f;
#pragma unroll
    for (int u = 0; u < 4; u++) { v[u] = __expf(v[u] - m); sm += v[u]; }
#pragma unroll
    for (int o = 16; o > 0; o >>= 1) sm += __shfl_xor_sync(0xffffffffu, sm, o);
    float inv = 1.f / sm;
    __half* out = AC + (size_t)b * SQ * SQ + (size_t)s * SQ;
#pragma unroll
    for (int u = 0; u < 4; u++) out[lane + 32 * u] = __float2half_rn(v[u] * inv);
}

// ---------------------------------------------------------------------------
// Host-side fp16 GEMM dispatch (static smem, no attribute needed)
// ---------------------------------------------------------------------------
static void run_g16(int epi, int M, int N, int K,
                    const __half* A, int lda, size_t sA,
                    const __half* B, int ldb, size_t sB,
                    void* C, int ldc, size_t sC,
                    const float* bias, int batch)
{
    dim3 grid(N / 128, M / 128, batch), block(256);
    if (epi == 0)      tgemm16_kernel<0><<<grid, block>>>(M, N, K, A, lda, sA, B, ldb, sB, C, ldc, sC, bias);
    else if (epi == 1) tgemm16_kernel<1><<<grid, block>>>(M, N, K, A, lda, sA, B, ldb, sB, C, ldc, sC, bias);
    else               tgemm16_kernel<2><<<grid, block>>>(M, N, K, A, lda, sA, B, ldb, sB, C, ldc, sC, bias);
}

// ---------------------------------------------------------------------------
// kernel_launch
// ---------------------------------------------------------------------------
extern "C" void kernel_launch(void* const* d_in, const int* in_sizes, int n_in,
                              void* d_out, int out_size)
{
    (void)in_sizes; (void)n_in; (void)out_size;
    const int*   inQ   = (const int*)d_in[1];
    const int*   inC   = (const int*)d_in[2];
    const int*   inC2  = (const int*)d_in[3];
    const float* hidQ  = (const float*)d_in[4];
    const float* celQ  = (const float*)d_in[5];
    const float* hidC  = (const float*)d_in[6];
    const float* celC  = (const float*)d_in[7];
    const float* hidC2 = (const float*)d_in[8];
    const float* celC2 = (const float*)d_in[9];
    const float* emb   = (const float*)d_in[10];
    const float* WihF  = (const float*)d_in[11];
    const float* WhhF  = (const float*)d_in[12];
    const float* bihF  = (const float*)d_in[13];
    const float* bhhF  = (const float*)d_in[14];
    const float* WihB  = (const float*)d_in[15];
    const float* WhhB  = (const float*)d_in[16];
    const float* bihB  = (const float*)d_in[17];
    const float* bhhB  = (const float*)d_in[18];
    const float* S1W   = (const float*)d_in[19];
    const float* S1b   = (const float*)d_in[20];
    float* out = (float*)d_out;

    void *pXh, *pXpF, *pXpB, *pWFh, *pWBh, *pS1h, *pBf, *pBb, *pY, *pYh,
         *pCt, *pYqT, *pMQT, *pHm, *pAQ, *pAC, *pBar;
    cudaGetSymbolAddress(&pXh,  g_Xh);
    cudaGetSymbolAddress(&pXpF, g_XpreF);
    cudaGetSymbolAddress(&pXpB, g_XpreB);
    cudaGetSymbolAddress(&pWFh, g_WihFh);
    cudaGetSymbolAddress(&pWBh, g_WihBh);
    cudaGetSymbolAddress(&pS1h, g_S1Wh);
    cudaGetSymbolAddress(&pBf,  g_biasf);
    cudaGetSymbolAddress(&pBb,  g_biasb);
    cudaGetSymbolAddress(&pY,   g_Y);
    cudaGetSymbolAddress(&pYh,  g_Yh);
    cudaGetSymbolAddress(&pCt,  g_Ct);
    cudaGetSymbolAddress(&pYqT, g_YqT);
    cudaGetSymbolAddress(&pMQT, g_MQT);
    cudaGetSymbolAddress(&pHm,  g_Hm);
    cudaGetSymbolAddress(&pAQ,  g_AQ);
    cudaGetSymbolAddress(&pAC,  g_AC);
    cudaGetSymbolAddress(&pBar, g_bar);
    __half* Xh  = (__half*)pXh;
    float*  XpF = (float*)pXpF;
    float*  XpB = (float*)pXpB;
    __half* WFh = (__half*)pWFh;
    __half* WBh = (__half*)pWBh;
    __half* S1h = (__half*)pS1h;
    float*  Bf  = (float*)pBf;
    float*  Bb  = (float*)pBb;
    float*  Y   = (float*)pY;
    __half* Yh  = (__half*)pYh;
    __half* Ct  = (__half*)pCt;
    __half* YqT = (__half*)pYqT;
    __half* MQT = (__half*)pMQT;
    float*  Hm  = (float*)pHm;
    __half* AQ  = (__half*)pAQ;
    __half* AC  = (__half*)pAC;
    int*    bars = (int*)pBar;

    cudaFuncSetAttribute(lstm_mma_kernel,
                         cudaFuncAttributeMaxDynamicSharedMemorySize,
                         LSTM_SMEM_BYTES);

    // 1. prep: bias fold, barrier reset, fp16 weight copies
    prep_kernel<<<1024, 256>>>(bihF, bhhF, bihB, bhhB, WihF, WihB, S1W,
                               Bf, Bb, WFh, WBh, S1h, bars);

    // 2. embedding gather -> fp16 X
    embed_kernel<<<12288, 256>>>(inQ, inC, inC2, (const float4*)emb, Xh);

    // 3. input GEMMs: Xpre = X @ Wih^T + (bih+bhh)   (fp16 operands, fp32 out)
    run_g16(1, MX, G4, EE, Xh, EE, 0, WFh, EE, 0, XpF, G4, 0, Bf, 1);
    run_g16(1, MX, G4, EE, Xh, EE, 0, WBh, EE, 0, XpB, G4, 0, Bb, 1);

    // 4. recurrence (R10 verified, tf32, aggregate-barrier exchange)
    lstm_mma_kernel<<<96, 256, LSTM_SMEM_BYTES>>>(
        XpF, XpB, WhhF, WhhB,
        hidQ, celQ, hidC, celC, hidC2, celC2, Y, bars);

    // 4b. Y -> fp16 copy for downstream GEMM operands
    f2h_kernel<<<24576, 256>>>((const float4*)Y, (__half2*)Yh);

    // 5. Ct = tanh(Y_c @ S1_W^T + S1_b)  -> fp16
    run_g16(2, MBS, D2, D2, Yh + (size_t)1 * MBS * D2, D2, 0,
            S1h, D2, 0, Ct, D2, 0, S1b, 1);
    run_g16(2, MBS, D2, D2, Yh + (size_t)2 * MBS * D2, D2, 0,
            S1h, D2, 0, Ct + (size_t)MBS * D2, D2, 0, S1b, 1);

    // 5b. Yq^T (fp32 Y -> fp16 transposed)
    {
        dim3 tg(D2 / 32, SQ / 32, BB), tb(32, 8);
        transpose_kernel<<<tg, tb>>>(Y, YqT);
    }

    // 6. attention for pairs (Q,C) and (Q,C2)
    for (int p = 0; p < 2; p++) {
        run_g16(0, SQ, SQ, D2,
                Yh, D2, (size_t)SQ * D2,
                Ct + (size_t)p * MBS * D2, D2, (size_t)SQ * D2,
                Hm, SQ, (size_t)SQ * SQ, nullptr, BB);
        row_softmax<<<2048, 256>>>(Hm, AQ);
        col_softmax<<<2048, 256>>>(Hm, AC);
        float* outMQ = out + (size_t)(2 * p) * OUTREG;
        float* outMC = out + (size_t)(2 * p + 1) * OUTREG;
        run_g16(0, SQ, D2, SQ,
                AQ, SQ, (size_t)SQ * SQ,
                YqT, SQ, (size_t)SQ * D2,
                outMQ, D2, (size_t)SQ * D2, nullptr, BB);
        {
            dim3 tg(D2 / 32, SQ / 32, BB), tb(32, 8);
            transpose_kernel<<<tg, tb>>>(outMQ, MQT);
        }
        run_g16(0, SQ, D2, SQ,
                AC, SQ, (size_t)SQ * SQ,
                MQT, SQ, (size_t)SQ * D2,
                outMC, D2, (size_t)SQ * D2, nullptr, BB);
    }
}

// round 15
// speedup vs baseline: 1.2813x; 1.1094x over previous
#include <cuda_runtime.h>
#include <cuda_fp16.h>
#include <cstdint>
#include <math.h>

// ---------------------------------------------------------------------------
// Problem constants
// ---------------------------------------------------------------------------
#define SQ   128            // seq len
#define BB   128            // batch
#define EE   256            // embed dim
#define HH   256            // hidden
#define G4   1024           // 4*H
#define D2   512            // 2*H
#define MBS  (BB*SQ)        // 16384
#define MX   (3*MBS)        // 49152 rows of X
#define OUTREG (BB*SQ*D2)   // 8388608 floats per output tensor

// fp16 LSTM-mma geometry: word (=half2) row stride 132 (4 mod 32 -> conflict-free)
#define WP16 132
#define GPAD 132
// smW[128][132]w + smH[64][132]w (smG fp32 aliases smH: 64*132*4 = same bytes)
#define LSTM_SMEM_BYTES ((128*WP16 + 64*WP16) * 4)   // 101,376 B

// fp16 tgemm smem geometry (verified R14)
#define TGW 20
#define TGH_BUF (128 * TGW)

// ---------------------------------------------------------------------------
// Device scratch
// ---------------------------------------------------------------------------
__device__ __half g_Xh  [3*MBS*EE];     //  25 MB  embedded inputs (fp16)
__device__ float  g_XpreF[3*MBS*G4];    // 201 MB  X@Wih_f^T + bias_f (fp32)
__device__ float  g_XpreB[3*MBS*G4];    // 201 MB
__device__ __half g_WihFh[G4*EE];       // fp16 Wih_f
__device__ __half g_WihBh[G4*EE];       // fp16 Wih_b
__device__ __half g_S1Wh [D2*D2];       // fp16 S1_W
__device__ float  g_biasf[G4];
__device__ float  g_biasb[G4];
__device__ float  g_Y    [3*MBS*D2];    // 100 MB  BiLSTM outputs (fp16-rounded fp32)
__device__ __half g_Yh   [3*MBS*D2];    //  50 MB  fp16 copy of Y
__device__ __half g_Ct   [2*MBS*D2];    //  34 MB  tanh(S1(C)) (fp16)
__device__ __half g_YqT  [MBS*D2];      //  17 MB  transpose of Q stream (fp16)
__device__ __half g_MQT  [MBS*D2];      //  17 MB  transpose of MQ (fp16)
__device__ float  g_Hm   [BB*SQ*SQ];    // 8.4 MB  logits (fp32)
__device__ __half g_AQ   [BB*SQ*SQ];
__device__ __half g_AC   [BB*SQ*SQ];
__device__ int    g_bar  [12];

// ---------------------------------------------------------------------------
// helpers
// ---------------------------------------------------------------------------
__device__ __forceinline__ void mma_f16(float* d, const unsigned a[4],
                                        unsigned b0, unsigned b1) {
    asm volatile(
        "mma.sync.aligned.m16n8k16.row.col.f32.f16.f16.f32 "
        "{%0,%1,%2,%3},{%4,%5,%6,%7},{%8,%9},{%0,%1,%2,%3};"
        : "+f"(d[0]), "+f"(d[1]), "+f"(d[2]), "+f"(d[3])
        : "r"(a[0]), "r"(a[1]), "r"(a[2]), "r"(a[3]), "r"(b0), "r"(b1));
}
__device__ __forceinline__ unsigned smem_u32(const void* p) {
    unsigned a;
    asm("{ .reg .u64 t; cvta.to.shared.u64 t, %1; cvt.u32.u64 %0, t; }"
        : "=r"(a) : "l"(p));
    return a;
}
__device__ __forceinline__ void prefetchL2(const void* p) {
    asm volatile("prefetch.global.L2 [%0];" :: "l"(p));
}
__device__ __forceinline__ unsigned pack_h2(float a, float b) {
    __half2 h = __floats2half2_rn(a, b);
    return *(unsigned*)&h;
}

// ---------------------------------------------------------------------------
// Prep: bias fold, barrier reset, fp16 weight copies
// ---------------------------------------------------------------------------
__global__ void prep_kernel(const float* __restrict__ bihF, const float* __restrict__ bhhF,
                            const float* __restrict__ bihB, const float* __restrict__ bhhB,
                            const float* __restrict__ WihF, const float* __restrict__ WihB,
                            const float* __restrict__ S1W,
                            float* __restrict__ biasf, float* __restrict__ biasb,
                            __half* __restrict__ wihFh, __half* __restrict__ wihBh,
                            __half* __restrict__ s1wh, int* __restrict__ bars)
{
    int gid = blockIdx.x * 256 + threadIdx.x;   // 0..262143
    wihFh[gid] = __float2half_rn(WihF[gid]);
    wihBh[gid] = __float2half_rn(WihB[gid]);
    s1wh [gid] = __float2half_rn(S1W [gid]);
    if (gid < G4) {
        biasf[gid] = bihF[gid] + bhhF[gid];
        biasb[gid] = bihB[gid] + bhhB[gid];
    }
    if (gid < 12) bars[gid] = 0;
}

// ---------------------------------------------------------------------------
// Embedding gather -> fp16 X
// ---------------------------------------------------------------------------
__global__ void embed_kernel(const int* __restrict__ tq, const int* __restrict__ tc,
                             const int* __restrict__ tc2,
                             const float4* __restrict__ emb, __half* __restrict__ Xh)
{
    int gid = blockIdx.x * 256 + threadIdx.x;      // 3145728 total
    int c4  = gid & 63;
    int row = gid >> 6;
    int seq = row / MBS;
    int rb  = row - seq * MBS;
    int b   = rb >> 7, s = rb & 127;
    const int* tok = (seq == 0) ? tq : ((seq == 1) ? tc : tc2);
    int t = tok[s * BB + b];
    float4 v = emb[(size_t)t * 64 + c4];
    __half* dst = Xh + (size_t)row * EE + c4 * 4;
    *(__half2*)(dst)     = __floats2half2_rn(v.x, v.y);
    *(__half2*)(dst + 2) = __floats2half2_rn(v.z, v.w);
}

// ---------------------------------------------------------------------------
// fp32 -> fp16 convert (Y -> Yh); Y is fp16-pre-rounded so this is exact
// ---------------------------------------------------------------------------
__global__ void f2h_kernel(const float4* __restrict__ in, __half2* __restrict__ out)
{
    int gid = blockIdx.x * 256 + threadIdx.x;      // 6291456 float4s
    float4 v = in[gid];
    out[2 * gid]     = __floats2half2_rn(v.x, v.y);
    out[2 * gid + 1] = __floats2half2_rn(v.z, v.w);
}

// ---------------------------------------------------------------------------
// fp16 tensor-core GEMM, NT form (verified R14)
// EPI: 0 -> C fp32; 1 -> C fp32 + bias; 2 -> C __half = tanh(x+bias)
// ---------------------------------------------------------------------------
template<int EPI>
__global__ __launch_bounds__(256) void tgemm16_kernel(
    int M, int N, int K,
    const __half* __restrict__ A, int lda, size_t sA,
    const __half* __restrict__ B, int ldb, size_t sB,
    void* __restrict__ Cv, int ldc, size_t sC,
    const float* __restrict__ bias)
{
    __shared__ unsigned As[2][TGH_BUF];
    __shared__ unsigned Bs[2][TGH_BUF];

    int bx = blockIdx.x, by = blockIdx.y, bz = blockIdx.z;
    const __half* Ap = A + (size_t)bz * sA + (size_t)by * 128 * lda;
    const __half* Bp = B + (size_t)bz * sB + (size_t)bx * 128 * ldb;

    int tid = threadIdx.x, lane = tid & 31, warp = tid >> 5;
    int wm = warp & 3, wn = warp >> 2;
    int ly = lane >> 2, lx = lane & 3;

    float acc[2][8][4];
#pragma unroll
    for (int im = 0; im < 2; im++)
#pragma unroll
        for (int nt = 0; nt < 8; nt++)
#pragma unroll
            for (int j = 0; j < 4; j++) acc[im][nt][j] = 0.f;

    int NC = K >> 5;

    auto issue = [&](int kc, int b) {
        int k0 = kc * 32;
#pragma unroll
        for (int i = 0; i < 2; i++) {
            int seg = tid + 256 * i;
            int row = seg >> 2, s4 = (seg & 3) * 4;
            unsigned sa = smem_u32(&As[b][row * TGW + s4]);
            asm volatile("cp.async.cg.shared.global [%0], [%1], 16;"
                         :: "r"(sa), "l"(Ap + (size_t)row * lda + k0 + s4 * 2));
            unsigned sb = smem_u32(&Bs[b][row * TGW + s4]);
            asm volatile("cp.async.cg.shared.global [%0], [%1], 16;"
                         :: "r"(sb), "l"(Bp + (size_t)row * ldb + k0 + s4 * 2));
        }
        asm volatile("cp.async.commit_group;");
    };

    issue(0, 0);
    for (int kc = 0; kc < NC; kc++) {
        int b = kc & 1;
        if (kc + 1 < NC) {
            issue(kc + 1, b ^ 1);
            asm volatile("cp.async.wait_group 1;");
        } else {
            asm volatile("cp.async.wait_group 0;");
        }
        __syncthreads();

        const unsigned* Ab = As[b];
        const unsigned* Bb = Bs[b];
#pragma unroll
        for (int kk = 0; kk < 2; kk++) {
            int k8w = kk * 8;
            unsigned a[2][4];
#pragma unroll
            for (int im = 0; im < 2; im++) {
                int rb = wm * 32 + im * 16;
                a[im][0] = Ab[(rb + ly) * TGW + k8w + lx];
                a[im][1] = Ab[(rb + ly + 8) * TGW + k8w + lx];
                a[im][2] = Ab[(rb + ly) * TGW + k8w + lx + 4];
                a[im][3] = Ab[(rb + ly + 8) * TGW + k8w + lx + 4];
            }
#pragma unroll
            for (int nt = 0; nt < 8; nt++) {
                int n = wn * 64 + nt * 8 + ly;
                unsigned b0 = Bb[n * TGW + k8w + lx];
                unsigned b1 = Bb[n * TGW + k8w + lx + 4];
                mma_f16(acc[0][nt], a[0], b0, b1);
                mma_f16(acc[1][nt], a[1], b0, b1);
            }
        }
        __syncthreads();
    }

#pragma unroll
    for (int im = 0; im < 2; im++) {
#pragma unroll
        for (int nt = 0; nt < 8; nt++) {
            int n0 = wn * 64 + nt * 8 + lx * 2;
            int r0 = wm * 32 + im * 16 + ly;
            float2 v0 = make_float2(acc[im][nt][0], acc[im][nt][1]);
            float2 v1 = make_float2(acc[im][nt][2], acc[im][nt][3]);
            if constexpr (EPI >= 1) {
                float b0v = bias[bx * 128 + n0], b1v = bias[bx * 128 + n0 + 1];
                v0.x += b0v; v0.y += b1v; v1.x += b0v; v1.y += b1v;
            }
            if constexpr (EPI == 2) {
                __half* Ch = (__half*)Cv + (size_t)bz * sC
                           + (size_t)by * 128 * ldc + (size_t)bx * 128;
                *(__half2*)&Ch[(size_t)r0 * ldc + n0] =
                    __floats2half2_rn(tanhf(v0.x), tanhf(v0.y));
                *(__half2*)&Ch[(size_t)(r0 + 8) * ldc + n0] =
                    __floats2half2_rn(tanhf(v1.x), tanhf(v1.y));
            } else {
                float* Cp = (float*)Cv + (size_t)bz * sC
                          + (size_t)by * 128 * ldc + (size_t)bx * 128;
                *reinterpret_cast<float2*>(&Cp[(size_t)r0 * ldc + n0]) = v0;
                *reinterpret_cast<float2*>(&Cp[(size_t)(r0 + 8) * ldc + n0]) = v1;
            }
        }
    }
}

// ---------------------------------------------------------------------------
// Batched transpose: fp32 in -> fp16 out
// ---------------------------------------------------------------------------
__global__ void transpose_kernel(const float* __restrict__ in, __half* __restrict__ out)
{
    __shared__ float tile[32][33];
    int b = blockIdx.z;
    const float* ip = in + (size_t)b * SQ * D2;
    __half* op = out + (size_t)b * SQ * D2;
    int c0 = blockIdx.x * 32, r0 = blockIdx.y * 32;
    int x = threadIdx.x, y = threadIdx.y;
#pragma unroll
    for (int j = 0; j < 32; j += 8)
        tile[y + j][x] = ip[(size_t)(r0 + y + j) * D2 + c0 + x];
    __syncthreads();
#pragma unroll
    for (int j = 0; j < 32; j += 8)
        op[(size_t)(c0 + y + j) * SQ + r0 + x] = __float2half_rn(tile[x][y + j]);
}

// ---------------------------------------------------------------------------
// LSTM recurrence — R10 verified structure, MMA ported to fp16 m16n8k16
// (fragment mapping verified by tgemm16 in R14). h rounded to fp16; smW/smH
// fp16 half2 words, stride WP16=132 (conflict-free). smG fp32 aliases smH.
// ---------------------------------------------------------------------------
__global__ __launch_bounds__(256) void lstm_mma_kernel(
    const float* __restrict__ xpreF, const float* __restrict__ xpreB,
    const float* __restrict__ WhhF, const float* __restrict__ WhhB,
    const float* __restrict__ h_q, const float* __restrict__ c_q,
    const float* __restrict__ h_c, const float* __restrict__ c_c,
    const float* __restrict__ h_c2, const float* __restrict__ c_c2,
    float* __restrict__ Y, int* __restrict__ bars)
{
    extern __shared__ unsigned sm[];
    unsigned* smW = sm;                      // [128][WP16] fp16 weights (words)
    unsigned* smH = sm + 128 * WP16;         // [64][WP16] fp16 h (words)
    float*    smG = (float*)smH;             // [64][GPAD] fp32 gates (aliased)
    __half*   smH16 = (__half*)smH;

    int bx  = blockIdx.x;
    int sd  = bx >> 4;
    int rem = bx & 15;
    int bg  = rem >> 3;
    int gg  = rem & 7;
    int seq = sd >> 1, dir = sd & 1;
    int grp = sd * 2 + bg;

    int tid  = threadIdx.x;
    int lane = tid & 31, warp = tid >> 5;
    int ly = lane >> 2, lx = lane & 3;
    int mt = warp & 3;                       // m-tile (16 rows)
    int nh = warp >> 2;                      // n-half (64 gate-cols)

    const float* xpre = (dir ? xpreB : xpreF) + (size_t)seq * MBS * G4;
    const float* Whh  = dir ? WhhB : WhhF;
    const float* h0p  = (seq == 0) ? h_q : ((seq == 1) ? h_c : h_c2);
    const float* c0p  = (seq == 0) ? c_q : ((seq == 1) ? c_c : c_c2);

    // ---- weights into smem as fp16 words: row r = gate-row, 128 words of K ----
    for (int i = tid; i < 128 * 128; i += 256) {
        int r = i >> 7, w = i & 127;
        int g = r >> 5, u_ = r & 31;
        const float* src = &Whh[(size_t)(g * 256 + gg * 32 + u_) * 256 + w * 2];
        smW[r * WP16 + w] = pack_h2(src[0], src[1]);
    }
    // ---- initial h into smem (fp16) ----
    for (int i = tid; i < 64 * 64; i += 256) {
        int r = i >> 6, c4 = (i & 63) * 4;
        float4 v = *(const float4*)&h0p[((size_t)(dir * BB + bg * 64 + r)) * HH + c4];
        uint2 w; w.x = pack_h2(v.x, v.y); w.y = pack_h2(v.z, v.w);
        *(uint2*)&smH[r * WP16 + c4 / 2] = w;
    }
    int u  = tid & 31;
    int mb = warp * 8;
    float cst[8];
#pragma unroll
    for (int p = 0; p < 8; p++)
        cst[p] = c0p[((size_t)(dir * BB + bg * 64 + mb + p)) * HH + gg * 32 + u];
    __syncthreads();

    volatile int* vb = (volatile int*)(bars + grp);
    float hv[8];

    for (int t = 0; t < SQ; t++) {
        int te = dir ? (SQ - 1 - t) : t;

        // ---- prefetch this step's xpre values into L2 during MMA ----
#pragma unroll
        for (int p = 0; p < 8; p++) {
            const float* xp = &xpre[(((size_t)(bg * 64 + mb + p)) * SQ + te) * G4 + gg * 32 + u];
            prefetchL2(xp);
            prefetchL2(xp + 256);
            prefetchL2(xp + 512);
            prefetchL2(xp + 768);
        }

        // ---- MMA phase: fp16 m16n8k16, 16 K-chunks ----
        float acc[8][4];
#pragma unroll
        for (int n = 0; n < 8; n++)
#pragma unroll
            for (int j = 0; j < 4; j++) acc[n][j] = 0.f;

        const unsigned* hA = smH + (mt * 16 + ly) * WP16 + lx;
#pragma unroll 4
        for (int kc = 0; kc < 16; kc++) {
            int k8w = kc * 8;
            unsigned a[4];
            a[0] = hA[k8w];
            a[1] = hA[k8w + 8 * WP16];
            a[2] = hA[k8w + 4];
            a[3] = hA[k8w + 8 * WP16 + 4];
#pragma unroll
            for (int nt = 0; nt < 8; nt++) {
                const unsigned* wB = smW + (nh * 64 + nt * 8 + ly) * WP16 + k8w + lx;
                mma_f16(acc[nt], a, wB[0], wB[4]);
            }
        }
        __syncthreads();          // h reads done; G overwrites region

        // ---- write G tile (fp32) to smem ----
#pragma unroll
        for (int nt = 0; nt < 8; nt++) {
            int n0 = nh * 64 + nt * 8 + lx * 2;
            int r0 = mt * 16 + ly;
            *(float2*)&smG[r0 * GPAD + n0]       = make_float2(acc[nt][0], acc[nt][1]);
            *(float2*)&smG[(r0 + 8) * GPAD + n0] = make_float2(acc[nt][2], acc[nt][3]);
        }
        __syncthreads();

        // ---- gate nonlinearity; h rounded to fp16; Y gets rounded fp32 ----
#pragma unroll
        for (int p = 0; p < 8; p++) {
            int m = mb + p;
            const float* xp = &xpre[(((size_t)(bg * 64 + m)) * SQ + te) * G4 + gg * 32 + u];
            float gi = smG[m * GPAD +      u] + xp[0];
            float gf = smG[m * GPAD + 32 + u] + xp[256];
            float gc = smG[m * GPAD + 64 + u] + xp[512];
            float go = smG[m * GPAD + 96 + u] + xp[768];
            float i_ = 1.f / (1.f + __expf(-gi));
            float f_ = 1.f / (1.f + __expf(-gf));
            float g_ = tanhf(gc);
            float o_ = 1.f / (1.f + __expf(-go));
            float c  = f_ * cst[p] + i_ * g_;
            cst[p] = c;
            float h = __half2float(__float2half_rn(o_ * tanhf(c)));
            hv[p] = h;
            Y[(((size_t)(seq * BB + bg * 64 + m)) * SQ + te) * D2 + dir * HH + gg * 32 + u] = h;
        }

        __threadfence();
        __syncthreads();
        if (tid == 0) {
            atomicAdd(bars + grp, 1);
            int target = 8 * (t + 1);
            while (*vb < target) { }
            __threadfence();
        }
        __syncthreads();

        // ---- own chunk into smH from registers (fp16, exact) ----
#pragma unroll
        for (int p = 0; p < 8; p++)
            smH16[(mb + p) * (2 * WP16) + gg * 32 + u] = __float2half_rn(hv[p]);
        // ---- reload other 7 chunks (Y fp16-pre-rounded: exact) ----
        for (int i = tid; i < 64 * 64; i += 256) {
            if (((i & 63) >> 3) == gg) continue;
            int r = i >> 6, c4 = (i & 63) * 4;
            float4 v = __ldcg((const float4*)&Y[
                (((size_t)(seq * BB + bg * 64 + r)) * SQ + te) * D2 + dir * HH + c4]);
            uint2 w; w.x = pack_h2(v.x, v.y); w.y = pack_h2(v.z, v.w);
            *(uint2*)&smH[r * WP16 + c4 / 2] = w;
        }
        __syncthreads();
    }
}

// ---------------------------------------------------------------------------
// Softmax kernels (fp16 outputs)
// ---------------------------------------------------------------------------
__global__ void row_softmax(const float* __restrict__ Hm, __half* __restrict__ AQ)
{
    int warp = (blockIdx.x * blockDim.x + threadIdx.x) >> 5;
    int lane = threadIdx.x & 31;
    const float* base = Hm + (size_t)warp * SQ;
    float v[4], m = -1e30f;
#pragma unroll
    for (int u = 0; u < 4; u++) { v[u] = base[lane + 32 * u]; m = fmaxf(m, v[u]); }
#pragma unroll
    for (int o = 16; o > 0; o >>= 1) m = fmaxf(m, __shfl_xor_sync(0xffffffffu, m, o));
    float s = 0.f;
#pragma unroll
    for (int u = 0; u < 4; u++) { v[u] = __expf(v[u] - m); s += v[u]; }
#pragma unroll
    for (int o = 16; o > 0; o >>= 1) s += __shfl_xor_sync(0xffffffffu, s, o);
    float inv = 1.f / s;
    __half* out = AQ + (size_t)warp * SQ;
#pragma unroll
    for (int u = 0; u < 4; u++) out[lane + 32 * u] = __float2half_rn(v[u] * inv);
}

__global__ void col_softmax(const float* __restrict__ Hm, __half* __restrict__ AC)
{
    int warp = (blockIdx.x * blockDim.x + threadIdx.x) >> 5;
    int lane = threadIdx.x & 31;
    int b = warp >> 7, s = warp & 127;
    const float* base = Hm + (size_t)b * SQ * SQ + s;
    float v[4], m = -1e30f;
#pragma unroll
    for (int u = 0; u < 4; u++) { v[u] = base[(size_t)(lane + 32 * u) * SQ]; m = fmaxf(m, v[u]); }
#pragma unroll
    for (int o = 16; o > 0; o >>= 1) m = fmaxf(m, __shfl_xor_sync(0xffffffffu, m, o));
    float sm = 0.f;
#pragma unroll
    for (int u = 0; u < 4; u++) { v[u] = __expf(v[u] - m); sm += v[u]; }
#pragma unroll
    for (int o = 16; o > 0; o >>= 1) sm += __shfl_xor_sync(0xffffffffu, sm, o);
    float inv = 1.f / sm;
    __half* out = AC + (size_t)b * SQ * SQ + (size_t)s * SQ;
#pragma unroll
    for (int u = 0; u < 4; u++) out[lane + 32 * u] = __float2half_rn(v[u] * inv);
}

// ---------------------------------------------------------------------------
// Host-side fp16 GEMM dispatch
// ---------------------------------------------------------------------------
static void run_g16(int epi, int M, int N, int K,
                    const __half* A, int lda, size_t sA,
                    const __half* B, int ldb, size_t sB,
                    void* C, int ldc, size_t sC,
                    const float* bias, int batch)
{
    dim3 grid(N / 128, M / 128, batch), block(256);
    if (epi == 0)      tgemm16_kernel<0><<<grid, block>>>(M, N, K, A, lda, sA, B, ldb, sB, C, ldc, sC, bias);
    else if (epi == 1) tgemm16_kernel<1><<<grid, block>>>(M, N, K, A, lda, sA, B, ldb, sB, C, ldc, sC, bias);
    else               tgemm16_kernel<2><<<grid, block>>>(M, N, K, A, lda, sA, B, ldb, sB, C, ldc, sC, bias);
}

// ---------------------------------------------------------------------------
// kernel_launch
// ---------------------------------------------------------------------------
extern "C" void kernel_launch(void* const* d_in, const int* in_sizes, int n_in,
                              void* d_out, int out_size)
{
    (void)in_sizes; (void)n_in; (void)out_size;
    const int*   inQ   = (const int*)d_in[1];
    const int*   inC   = (const int*)d_in[2];
    const int*   inC2  = (const int*)d_in[3];
    const float* hidQ  = (const float*)d_in[4];
    const float* celQ  = (const float*)d_in[5];
    const float* hidC  = (const float*)d_in[6];
    const float* celC  = (const float*)d_in[7];
    const float* hidC2 = (const float*)d_in[8];
    const float* celC2 = (const float*)d_in[9];
    const float* emb   = (const float*)d_in[10];
    const float* WihF  = (const float*)d_in[11];
    const float* WhhF  = (const float*)d_in[12];
    const float* bihF  = (const float*)d_in[13];
    const float* bhhF  = (const float*)d_in[14];
    const float* WihB  = (const float*)d_in[15];
    const float* WhhB  = (const float*)d_in[16];
    const float* bihB  = (const float*)d_in[17];
    const float* bhhB  = (const float*)d_in[18];
    const float* S1W   = (const float*)d_in[19];
    const float* S1b   = (const float*)d_in[20];
    float* out = (float*)d_out;

    void *pXh, *pXpF, *pXpB, *pWFh, *pWBh, *pS1h, *pBf, *pBb, *pY, *pYh,
         *pCt, *pYqT, *pMQT, *pHm, *pAQ, *pAC, *pBar;
    cudaGetSymbolAddress(&pXh,  g_Xh);
    cudaGetSymbolAddress(&pXpF, g_XpreF);
    cudaGetSymbolAddress(&pXpB, g_XpreB);
    cudaGetSymbolAddress(&pWFh, g_WihFh);
    cudaGetSymbolAddress(&pWBh, g_WihBh);
    cudaGetSymbolAddress(&pS1h, g_S1Wh);
    cudaGetSymbolAddress(&pBf,  g_biasf);
    cudaGetSymbolAddress(&pBb,  g_biasb);
    cudaGetSymbolAddress(&pY,   g_Y);
    cudaGetSymbolAddress(&pYh,  g_Yh);
    cudaGetSymbolAddress(&pCt,  g_Ct);
    cudaGetSymbolAddress(&pYqT, g_YqT);
    cudaGetSymbolAddress(&pMQT, g_MQT);
    cudaGetSymbolAddress(&pHm,  g_Hm);
    cudaGetSymbolAddress(&pAQ,  g_AQ);
    cudaGetSymbolAddress(&pAC,  g_AC);
    cudaGetSymbolAddress(&pBar, g_bar);
    __half* Xh  = (__half*)pXh;
    float*  XpF = (float*)pXpF;
    float*  XpB = (float*)pXpB;
    __half* WFh = (__half*)pWFh;
    __half* WBh = (__half*)pWBh;
    __half* S1h = (__half*)pS1h;
    float*  Bf  = (float*)pBf;
    float*  Bb  = (float*)pBb;
    float*  Y   = (float*)pY;
    __half* Yh  = (__half*)pYh;
    __half* Ct  = (__half*)pCt;
    __half* YqT = (__half*)pYqT;
    __half* MQT = (__half*)pMQT;
    float*  Hm  = (float*)pHm;
    __half* AQ  = (__half*)pAQ;
    __half* AC  = (__half*)pAC;
    int*    bars = (int*)pBar;

    cudaFuncSetAttribute(lstm_mma_kernel,
                         cudaFuncAttributeMaxDynamicSharedMemorySize,
                         LSTM_SMEM_BYTES);

    // 1. prep: bias fold, barrier reset, fp16 weight copies
    prep_kernel<<<1024, 256>>>(bihF, bhhF, bihB, bhhB, WihF, WihB, S1W,
                               Bf, Bb, WFh, WBh, S1h, bars);

    // 2. embedding gather -> fp16 X
    embed_kernel<<<12288, 256>>>(inQ, inC, inC2, (const float4*)emb, Xh);

    // 3. input GEMMs: Xpre = X @ Wih^T + (bih+bhh)
    run_g16(1, MX, G4, EE, Xh, EE, 0, WFh, EE, 0, XpF, G4, 0, Bf, 1);
    run_g16(1, MX, G4, EE, Xh, EE, 0, WBh, EE, 0, XpB, G4, 0, Bb, 1);

    // 4. recurrence (fp16 MMA, 96 resident CTAs, aggregate-barrier exchange)
    lstm_mma_kernel<<<96, 256, LSTM_SMEM_BYTES>>>(
        XpF, XpB, WhhF, WhhB,
        hidQ, celQ, hidC, celC, hidC2, celC2, Y, bars);

    // 4b. Y -> fp16 copy (exact: Y is fp16-pre-rounded)
    f2h_kernel<<<24576, 256>>>((const float4*)Y, (__half2*)Yh);

    // 5. Ct = tanh(Y_c @ S1_W^T + S1_b)  -> fp16
    run_g16(2, MBS, D2, D2, Yh + (size_t)1 * MBS * D2, D2, 0,
            S1h, D2, 0, Ct, D2, 0, S1b, 1);
    run_g16(2, MBS, D2, D2, Yh + (size_t)2 * MBS * D2, D2, 0,
            S1h, D2, 0, Ct + (size_t)MBS * D2, D2, 0, S1b, 1);

    // 5b. Yq^T
    {
        dim3 tg(D2 / 32, SQ / 32, BB), tb(32, 8);
        transpose_kernel<<<tg, tb>>>(Y, YqT);
    }

    // 6. attention for pairs (Q,C) and (Q,C2)
    for (int p = 0; p < 2; p++) {
        run_g16(0, SQ, SQ, D2,
                Yh, D2, (size_t)SQ * D2,
                Ct + (size_t)p * MBS * D2, D2, (size_t)SQ * D2,
                Hm, SQ, (size_t)SQ * SQ, nullptr, BB);
        row_softmax<<<2048, 256>>>(Hm, AQ);
        col_softmax<<<2048, 256>>>(Hm, AC);
        float* outMQ = out + (size_t)(2 * p) * OUTREG;
        float* outMC = out + (size_t)(2 * p + 1) * OUTREG;
        run_g16(0, SQ, D2, SQ,
                AQ, SQ, (size_t)SQ * SQ,
                YqT, SQ, (size_t)SQ * D2,
                outMQ, D2, (size_t)SQ * D2, nullptr, BB);
        {
            dim3 tg(D2 / 32, SQ / 32, BB), tb(32, 8);
            transpose_kernel<<<tg, tb>>>(outMQ, MQT);
        }
        run_g16(0, SQ, D2, SQ,
                AC, SQ, (size_t)SQ * SQ,
                MQT, SQ, (size_t)SQ * D2,
                outMC, D2, (size_t)SQ * D2, nullptr, BB);
    }
}

// round 16
// speedup vs baseline: 1.3986x; 1.0916x over previous
#include <cuda_runtime.h>
#include <cuda_fp16.h>
#include <cstdint>
#include <math.h>

// ---------------------------------------------------------------------------
// Problem constants
// ---------------------------------------------------------------------------
#define SQ   128            // seq len
#define BB   128            // batch
#define EE   256            // embed dim
#define HH   256            // hidden
#define G4   1024           // 4*H
#define D2   512            // 2*H
#define MBS  (BB*SQ)        // 16384
#define MX   (3*MBS)        // 49152 rows of X
#define OUTREG (BB*SQ*D2)   // 8388608 floats per output tensor

// fp16 LSTM-mma geometry: word (=half2) row stride 132 (4 mod 32 -> conflict-free)
#define WP16 132
#define GPAD 132
// smW[128][132]w + smH[64][132]w + smG[64][132]f  (un-aliased)
#define LSTM_SMEM_BYTES ((128*WP16 + 64*WP16 + 64*GPAD) * 4)   // 135,168 B

// fp16 tgemm smem geometry (verified R14)
#define TGW 20
#define TGH_BUF (128 * TGW)

// ---------------------------------------------------------------------------
// Device scratch
// ---------------------------------------------------------------------------
__device__ __half g_Xh  [3*MBS*EE];     //  25 MB  embedded inputs (fp16)
__device__ float  g_XpreF[3*MBS*G4];    // 201 MB  X@Wih_f^T + bias_f (fp32)
__device__ float  g_XpreB[3*MBS*G4];    // 201 MB
__device__ __half g_WihFh[G4*EE];       // fp16 Wih_f
__device__ __half g_WihBh[G4*EE];       // fp16 Wih_b
__device__ __half g_S1Wh [D2*D2];       // fp16 S1_W
__device__ float  g_biasf[G4];
__device__ float  g_biasb[G4];
__device__ float  g_Y    [3*MBS*D2];    // 100 MB  BiLSTM outputs (fp16-rounded fp32)
__device__ __half g_Yh   [3*MBS*D2];    //  50 MB  fp16 copy of Y
__device__ __half g_Ct   [2*MBS*D2];    //  34 MB  tanh(S1(C)) (fp16)
__device__ __half g_YqT  [MBS*D2];      //  17 MB  transpose of Q stream (fp16)
__device__ __half g_MQT  [MBS*D2];      //  17 MB  transpose of MQ (fp16)
__device__ float  g_Hm   [BB*SQ*SQ];    // 8.4 MB  logits (fp32)
__device__ __half g_AQ   [BB*SQ*SQ];
__device__ __half g_AC   [BB*SQ*SQ];
__device__ int    g_bar  [12];

// ---------------------------------------------------------------------------
// helpers
// ---------------------------------------------------------------------------
__device__ __forceinline__ void mma_f16(float* d, const unsigned a[4],
                                        unsigned b0, unsigned b1) {
    asm volatile(
        "mma.sync.aligned.m16n8k16.row.col.f32.f16.f16.f32 "
        "{%0,%1,%2,%3},{%4,%5,%6,%7},{%8,%9},{%0,%1,%2,%3};"
        : "+f"(d[0]), "+f"(d[1]), "+f"(d[2]), "+f"(d[3])
        : "r"(a[0]), "r"(a[1]), "r"(a[2]), "r"(a[3]), "r"(b0), "r"(b1));
}
__device__ __forceinline__ unsigned smem_u32(const void* p) {
    unsigned a;
    asm("{ .reg .u64 t; cvta.to.shared.u64 t, %1; cvt.u32.u64 %0, t; }"
        : "=r"(a) : "l"(p));
    return a;
}
__device__ __forceinline__ void prefetchL2(const void* p) {
    asm volatile("prefetch.global.L2 [%0];" :: "l"(p));
}
__device__ __forceinline__ unsigned pack_h2(float a, float b) {
    __half2 h = __floats2half2_rn(a, b);
    return *(unsigned*)&h;
}
// fast sigmoid/tanh: EX2 + RCP-approx (rel err ~2^-22, negligible vs fp16)
__device__ __forceinline__ float fsig(float x) {
    return __fdividef(1.f, 1.f + __expf(-x));
}
__device__ __forceinline__ float ftanh(float x) {
    return fmaf(2.f, __fdividef(1.f, 1.f + __expf(-2.f * x)), -1.f);
}

// ---------------------------------------------------------------------------
// Prep: bias fold, barrier reset, fp16 weight copies
// ---------------------------------------------------------------------------
__global__ void prep_kernel(const float* __restrict__ bihF, const float* __restrict__ bhhF,
                            const float* __restrict__ bihB, const float* __restrict__ bhhB,
                            const float* __restrict__ WihF, const float* __restrict__ WihB,
                            const float* __restrict__ S1W,
                            float* __restrict__ biasf, float* __restrict__ biasb,
                            __half* __restrict__ wihFh, __half* __restrict__ wihBh,
                            __half* __restrict__ s1wh, int* __restrict__ bars)
{
    int gid = blockIdx.x * 256 + threadIdx.x;   // 0..262143
    wihFh[gid] = __float2half_rn(WihF[gid]);
    wihBh[gid] = __float2half_rn(WihB[gid]);
    s1wh [gid] = __float2half_rn(S1W [gid]);
    if (gid < G4) {
        biasf[gid] = bihF[gid] + bhhF[gid];
        biasb[gid] = bihB[gid] + bhhB[gid];
    }
    if (gid < 12) bars[gid] = 0;
}

// ---------------------------------------------------------------------------
// Embedding gather -> fp16 X
// ---------------------------------------------------------------------------
__global__ void embed_kernel(const int* __restrict__ tq, const int* __restrict__ tc,
                             const int* __restrict__ tc2,
                             const float4* __restrict__ emb, __half* __restrict__ Xh)
{
    int gid = blockIdx.x * 256 + threadIdx.x;      // 3145728 total
    int c4  = gid & 63;
    int row = gid >> 6;
    int seq = row / MBS;
    int rb  = row - seq * MBS;
    int b   = rb >> 7, s = rb & 127;
    const int* tok = (seq == 0) ? tq : ((seq == 1) ? tc : tc2);
    int t = tok[s * BB + b];
    float4 v = emb[(size_t)t * 64 + c4];
    __half* dst = Xh + (size_t)row * EE + c4 * 4;
    *(__half2*)(dst)     = __floats2half2_rn(v.x, v.y);
    *(__half2*)(dst + 2) = __floats2half2_rn(v.z, v.w);
}

// ---------------------------------------------------------------------------
// fp32 -> fp16 convert (Y -> Yh); exact (Y is fp16-pre-rounded)
// ---------------------------------------------------------------------------
__global__ void f2h_kernel(const float4* __restrict__ in, __half2* __restrict__ out)
{
    int gid = blockIdx.x * 256 + threadIdx.x;      // 6291456 float4s
    float4 v = in[gid];
    out[2 * gid]     = __floats2half2_rn(v.x, v.y);
    out[2 * gid + 1] = __floats2half2_rn(v.z, v.w);
}

// ---------------------------------------------------------------------------
// fp16 tensor-core GEMM, NT form (verified R14); EPI=2 now uses ftanh
// ---------------------------------------------------------------------------
template<int EPI>
__global__ __launch_bounds__(256) void tgemm16_kernel(
    int M, int N, int K,
    const __half* __restrict__ A, int lda, size_t sA,
    const __half* __restrict__ B, int ldb, size_t sB,
    void* __restrict__ Cv, int ldc, size_t sC,
    const float* __restrict__ bias)
{
    __shared__ unsigned As[2][TGH_BUF];
    __shared__ unsigned Bs[2][TGH_BUF];

    int bx = blockIdx.x, by = blockIdx.y, bz = blockIdx.z;
    const __half* Ap = A + (size_t)bz * sA + (size_t)by * 128 * lda;
    const __half* Bp = B + (size_t)bz * sB + (size_t)bx * 128 * ldb;

    int tid = threadIdx.x, lane = tid & 31, warp = tid >> 5;
    int wm = warp & 3, wn = warp >> 2;
    int ly = lane >> 2, lx = lane & 3;

    float acc[2][8][4];
#pragma unroll
    for (int im = 0; im < 2; im++)
#pragma unroll
        for (int nt = 0; nt < 8; nt++)
#pragma unroll
            for (int j = 0; j < 4; j++) acc[im][nt][j] = 0.f;

    int NC = K >> 5;

    auto issue = [&](int kc, int b) {
        int k0 = kc * 32;
#pragma unroll
        for (int i = 0; i < 2; i++) {
            int seg = tid + 256 * i;
            int row = seg >> 2, s4 = (seg & 3) * 4;
            unsigned sa = smem_u32(&As[b][row * TGW + s4]);
            asm volatile("cp.async.cg.shared.global [%0], [%1], 16;"
                         :: "r"(sa), "l"(Ap + (size_t)row * lda + k0 + s4 * 2));
            unsigned sb = smem_u32(&Bs[b][row * TGW + s4]);
            asm volatile("cp.async.cg.shared.global [%0], [%1], 16;"
                         :: "r"(sb), "l"(Bp + (size_t)row * ldb + k0 + s4 * 2));
        }
        asm volatile("cp.async.commit_group;");
    };

    issue(0, 0);
    for (int kc = 0; kc < NC; kc++) {
        int b = kc & 1;
        if (kc + 1 < NC) {
            issue(kc + 1, b ^ 1);
            asm volatile("cp.async.wait_group 1;");
        } else {
            asm volatile("cp.async.wait_group 0;");
        }
        __syncthreads();

        const unsigned* Ab = As[b];
        const unsigned* Bb = Bs[b];
#pragma unroll
        for (int kk = 0; kk < 2; kk++) {
            int k8w = kk * 8;
            unsigned a[2][4];
#pragma unroll
            for (int im = 0; im < 2; im++) {
                int rb = wm * 32 + im * 16;
                a[im][0] = Ab[(rb + ly) * TGW + k8w + lx];
                a[im][1] = Ab[(rb + ly + 8) * TGW + k8w + lx];
                a[im][2] = Ab[(rb + ly) * TGW + k8w + lx + 4];
                a[im][3] = Ab[(rb + ly + 8) * TGW + k8w + lx + 4];
            }
#pragma unroll
            for (int nt = 0; nt < 8; nt++) {
                int n = wn * 64 + nt * 8 + ly;
                unsigned b0 = Bb[n * TGW + k8w + lx];
                unsigned b1 = Bb[n * TGW + k8w + lx + 4];
                mma_f16(acc[0][nt], a[0], b0, b1);
                mma_f16(acc[1][nt], a[1], b0, b1);
            }
        }
        __syncthreads();
    }

#pragma unroll
    for (int im = 0; im < 2; im++) {
#pragma unroll
        for (int nt = 0; nt < 8; nt++) {
            int n0 = wn * 64 + nt * 8 + lx * 2;
            int r0 = wm * 32 + im * 16 + ly;
            float2 v0 = make_float2(acc[im][nt][0], acc[im][nt][1]);
            float2 v1 = make_float2(acc[im][nt][2], acc[im][nt][3]);
            if constexpr (EPI >= 1) {
                float b0v = bias[bx * 128 + n0], b1v = bias[bx * 128 + n0 + 1];
                v0.x += b0v; v0.y += b1v; v1.x += b0v; v1.y += b1v;
            }
            if constexpr (EPI == 2) {
                __half* Ch = (__half*)Cv + (size_t)bz * sC
                           + (size_t)by * 128 * ldc + (size_t)bx * 128;
                *(__half2*)&Ch[(size_t)r0 * ldc + n0] =
                    __floats2half2_rn(ftanh(v0.x), ftanh(v0.y));
                *(__half2*)&Ch[(size_t)(r0 + 8) * ldc + n0] =
                    __floats2half2_rn(ftanh(v1.x), ftanh(v1.y));
            } else {
                float* Cp = (float*)Cv + (size_t)bz * sC
                          + (size_t)by * 128 * ldc + (size_t)bx * 128;
                *reinterpret_cast<float2*>(&Cp[(size_t)r0 * ldc + n0]) = v0;
                *reinterpret_cast<float2*>(&Cp[(size_t)(r0 + 8) * ldc + n0]) = v1;
            }
        }
    }
}

// ---------------------------------------------------------------------------
// Batched transpose: fp32 in -> fp16 out
// ---------------------------------------------------------------------------
__global__ void transpose_kernel(const float* __restrict__ in, __half* __restrict__ out)
{
    __shared__ float tile[32][33];
    int b = blockIdx.z;
    const float* ip = in + (size_t)b * SQ * D2;
    __half* op = out + (size_t)b * SQ * D2;
    int c0 = blockIdx.x * 32, r0 = blockIdx.y * 32;
    int x = threadIdx.x, y = threadIdx.y;
#pragma unroll
    for (int j = 0; j < 32; j += 8)
        tile[y + j][x] = ip[(size_t)(r0 + y + j) * D2 + c0 + x];
    __syncthreads();
#pragma unroll
    for (int j = 0; j < 32; j += 8)
        op[(size_t)(c0 + y + j) * SQ + r0 + x] = __float2half_rn(tile[x][y + j]);
}

// ---------------------------------------------------------------------------
// LSTM recurrence — R15 verified structure; smG un-aliased (one fewer sync);
// fast transcendentals in the epilogue.
// ---------------------------------------------------------------------------
__global__ __launch_bounds__(256) void lstm_mma_kernel(
    const float* __restrict__ xpreF, const float* __restrict__ xpreB,
    const float* __restrict__ WhhF, const float* __restrict__ WhhB,
    const float* __restrict__ h_q, const float* __restrict__ c_q,
    const float* __restrict__ h_c, const float* __restrict__ c_c,
    const float* __restrict__ h_c2, const float* __restrict__ c_c2,
    float* __restrict__ Y, int* __restrict__ bars)
{
    extern __shared__ unsigned sm[];
    unsigned* smW = sm;                          // [128][WP16] fp16 weights
    unsigned* smH = sm + 128 * WP16;             // [64][WP16] fp16 h
    float*    smG = (float*)(sm + 128 * WP16 + 64 * WP16);   // [64][GPAD] fp32
    __half*   smH16 = (__half*)smH;

    int bx  = blockIdx.x;
    int sd  = bx >> 4;
    int rem = bx & 15;
    int bg  = rem >> 3;
    int gg  = rem & 7;
    int seq = sd >> 1, dir = sd & 1;
    int grp = sd * 2 + bg;

    int tid  = threadIdx.x;
    int lane = tid & 31, warp = tid >> 5;
    int ly = lane >> 2, lx = lane & 3;
    int mt = warp & 3;
    int nh = warp >> 2;

    const float* xpre = (dir ? xpreB : xpreF) + (size_t)seq * MBS * G4;
    const float* Whh  = dir ? WhhB : WhhF;
    const float* h0p  = (seq == 0) ? h_q : ((seq == 1) ? h_c : h_c2);
    const float* c0p  = (seq == 0) ? c_q : ((seq == 1) ? c_c : c_c2);

    for (int i = tid; i < 128 * 128; i += 256) {
        int r = i >> 7, w = i & 127;
        int g = r >> 5, u_ = r & 31;
        const float* src = &Whh[(size_t)(g * 256 + gg * 32 + u_) * 256 + w * 2];
        smW[r * WP16 + w] = pack_h2(src[0], src[1]);
    }
    for (int i = tid; i < 64 * 64; i += 256) {
        int r = i >> 6, c4 = (i & 63) * 4;
        float4 v = *(const float4*)&h0p[((size_t)(dir * BB + bg * 64 + r)) * HH + c4];
        uint2 w; w.x = pack_h2(v.x, v.y); w.y = pack_h2(v.z, v.w);
        *(uint2*)&smH[r * WP16 + c4 / 2] = w;
    }
    int u  = tid & 31;
    int mb = warp * 8;
    float cst[8];
#pragma unroll
    for (int p = 0; p < 8; p++)
        cst[p] = c0p[((size_t)(dir * BB + bg * 64 + mb + p)) * HH + gg * 32 + u];
    __syncthreads();

    volatile int* vb = (volatile int*)(bars + grp);
    float hv[8];

    for (int t = 0; t < SQ; t++) {
        int te = dir ? (SQ - 1 - t) : t;

        // ---- prefetch this step's xpre values into L2 during MMA ----
#pragma unroll
        for (int p = 0; p < 8; p++) {
            const float* xp = &xpre[(((size_t)(bg * 64 + mb + p)) * SQ + te) * G4 + gg * 32 + u];
            prefetchL2(xp);
            prefetchL2(xp + 256);
            prefetchL2(xp + 512);
            prefetchL2(xp + 768);
        }

        // ---- MMA phase: fp16 m16n8k16 ----
        float acc[8][4];
#pragma unroll
        for (int n = 0; n < 8; n++)
#pragma unroll
            for (int j = 0; j < 4; j++) acc[n][j] = 0.f;

        const unsigned* hA = smH + (mt * 16 + ly) * WP16 + lx;
#pragma unroll 4
        for (int kc = 0; kc < 16; kc++) {
            int k8w = kc * 8;
            unsigned a[4];
            a[0] = hA[k8w];
            a[1] = hA[k8w + 8 * WP16];
            a[2] = hA[k8w + 4];
            a[3] = hA[k8w + 8 * WP16 + 4];
#pragma unroll
            for (int nt = 0; nt < 8; nt++) {
                const unsigned* wB = smW + (nh * 64 + nt * 8 + ly) * WP16 + k8w + lx;
                mma_f16(acc[nt], a, wB[0], wB[4]);
            }
        }
        // smG is its own buffer now: no sync needed before writing it
#pragma unroll
        for (int nt = 0; nt < 8; nt++) {
            int n0 = nh * 64 + nt * 8 + lx * 2;
            int r0 = mt * 16 + ly;
            *(float2*)&smG[r0 * GPAD + n0]       = make_float2(acc[nt][0], acc[nt][1]);
            *(float2*)&smG[(r0 + 8) * GPAD + n0] = make_float2(acc[nt][2], acc[nt][3]);
        }
        __syncthreads();

        // ---- gate nonlinearity (fast transcendentals); h fp16-rounded ----
#pragma unroll
        for (int p = 0; p < 8; p++) {
            int m = mb + p;
            const float* xp = &xpre[(((size_t)(bg * 64 + m)) * SQ + te) * G4 + gg * 32 + u];
            float gi = smG[m * GPAD +      u] + xp[0];
            float gf = smG[m * GPAD + 32 + u] + xp[256];
            float gc = smG[m * GPAD + 64 + u] + xp[512];
            float go = smG[m * GPAD + 96 + u] + xp[768];
            float i_ = fsig(gi);
            float f_ = fsig(gf);
            float g_ = ftanh(gc);
            float o_ = fsig(go);
            float c  = f_ * cst[p] + i_ * g_;
            cst[p] = c;
            float h = __half2float(__float2half_rn(o_ * ftanh(c)));
            hv[p] = h;
            Y[(((size_t)(seq * BB + bg * 64 + m)) * SQ + te) * D2 + dir * HH + gg * 32 + u] = h;
        }

        __threadfence();
        __syncthreads();
        if (tid == 0) {
            atomicAdd(bars + grp, 1);
            int target = 8 * (t + 1);
            while (*vb < target) { }
            __threadfence();
        }
        __syncthreads();

        // ---- own chunk into smH from registers (fp16, exact) ----
#pragma unroll
        for (int p = 0; p < 8; p++)
            smH16[(mb + p) * (2 * WP16) + gg * 32 + u] = __float2half_rn(hv[p]);
        // ---- reload other 7 chunks (Y fp16-pre-rounded: exact) ----
        for (int i = tid; i < 64 * 64; i += 256) {
            if (((i & 63) >> 3) == gg) continue;
            int r = i >> 6, c4 = (i & 63) * 4;
            float4 v = __ldcg((const float4*)&Y[
                (((size_t)(seq * BB + bg * 64 + r)) * SQ + te) * D2 + dir * HH + c4]);
            uint2 w; w.x = pack_h2(v.x, v.y); w.y = pack_h2(v.z, v.w);
            *(uint2*)&smH[r * WP16 + c4 / 2] = w;
        }
        __syncthreads();
    }
}

// ---------------------------------------------------------------------------
// Softmax kernels (fp16 outputs)
// ---------------------------------------------------------------------------
__global__ void row_softmax(const float* __restrict__ Hm, __half* __restrict__ AQ)
{
    int warp = (blockIdx.x * blockDim.x + threadIdx.x) >> 5;
    int lane = threadIdx.x & 31;
    const float* base = Hm + (size_t)warp * SQ;
    float v[4], m = -1e30f;
#pragma unroll
    for (int u = 0; u < 4; u++) { v[u] = base[lane + 32 * u]; m = fmaxf(m, v[u]); }
#pragma unroll
    for (int o = 16; o > 0; o >>= 1) m = fmaxf(m, __shfl_xor_sync(0xffffffffu, m, o));
    float s = 0.f;
#pragma unroll
    for (int u = 0; u < 4; u++) { v[u] = __expf(v[u] - m); s += v[u]; }
#pragma unroll
    for (int o = 16; o > 0; o >>= 1) s += __shfl_xor_sync(0xffffffffu, s, o);
    float inv = 1.f / s;
    __half* out = AQ + (size_t)warp * SQ;
#pragma unroll
    for (int u = 0; u < 4; u++) out[lane + 32 * u] = __float2half_rn(v[u] * inv);
}

__global__ void col_softmax(const float* __restrict__ Hm, __half* __restrict__ AC)
{
    int warp = (blockIdx.x * blockDim.x + threadIdx.x) >> 5;
    int lane = threadIdx.x & 31;
    int b = warp >> 7, s = warp & 127;
    const float* base = Hm + (size_t)b * SQ * SQ + s;
    float v[4], m = -1e30f;
#pragma unroll
    for (int u = 0; u < 4; u++) { v[u] = base[(size_t)(lane + 32 * u) * SQ]; m = fmaxf(m, v[u]); }
#pragma unroll
    for (int o = 16; o > 0; o >>= 1) m = fmaxf(m, __shfl_xor_sync(0xffffffffu, m, o));
    float sm = 0.f;
#pragma unroll
    for (int u = 0; u < 4; u++) { v[u] = __expf(v[u] - m); sm += v[u]; }
#pragma unroll
    for (int o = 16; o > 0; o >>= 1) sm += __shfl_xor_sync(0xffffffffu, sm, o);
    float inv = 1.f / sm;
    __half* out = AC + (size_t)b * SQ * SQ + (size_t)s * SQ;
#pragma unroll
    for (int u = 0; u < 4; u++) out[lane + 32 * u] = __float2half_rn(v[u] * inv);
}

// ---------------------------------------------------------------------------
// Host-side fp16 GEMM dispatch
// ---------------------------------------------------------------------------
static void run_g16(int epi, int M, int N, int K,
                    const __half* A, int lda, size_t sA,
                    const __half* B, int ldb, size_t sB,
                    void* C, int ldc, size_t sC,
                    const float* bias, int batch)
{
    dim3 grid(N / 128, M / 128, batch), block(256);
    if (epi == 0)      tgemm16_kernel<0><<<grid, block>>>(M, N, K, A, lda, sA, B, ldb, sB, C, ldc, sC, bias);
    else if (epi == 1) tgemm16_kernel<1><<<grid, block>>>(M, N, K, A, lda, sA, B, ldb, sB, C, ldc, sC, bias);
    else               tgemm16_kernel<2><<<grid, block>>>(M, N, K, A, lda, sA, B, ldb, sB, C, ldc, sC, bias);
}

// ---------------------------------------------------------------------------
// kernel_launch
// ---------------------------------------------------------------------------
extern "C" void kernel_launch(void* const* d_in, const int* in_sizes, int n_in,
                              void* d_out, int out_size)
{
    (void)in_sizes; (void)n_in; (void)out_size;
    const int*   inQ   = (const int*)d_in[1];
    const int*   inC   = (const int*)d_in[2];
    const int*   inC2  = (const int*)d_in[3];
    const float* hidQ  = (const float*)d_in[4];
    const float* celQ  = (const float*)d_in[5];
    const float* hidC  = (const float*)d_in[6];
    const float* celC  = (const float*)d_in[7];
    const float* hidC2 = (const float*)d_in[8];
    const float* celC2 = (const float*)d_in[9];
    const float* emb   = (const float*)d_in[10];
    const float* WihF  = (const float*)d_in[11];
    const float* WhhF  = (const float*)d_in[12];
    const float* bihF  = (const float*)d_in[13];
    const float* bhhF  = (const float*)d_in[14];
    const float* WihB  = (const float*)d_in[15];
    const float* WhhB  = (const float*)d_in[16];
    const float* bihB  = (const float*)d_in[17];
    const float* bhhB  = (const float*)d_in[18];
    const float* S1W   = (const float*)d_in[19];
    const float* S1b   = (const float*)d_in[20];
    float* out = (float*)d_out;

    void *pXh, *pXpF, *pXpB, *pWFh, *pWBh, *pS1h, *pBf, *pBb, *pY, *pYh,
         *pCt, *pYqT, *pMQT, *pHm, *pAQ, *pAC, *pBar;
    cudaGetSymbolAddress(&pXh,  g_Xh);
    cudaGetSymbolAddress(&pXpF, g_XpreF);
    cudaGetSymbolAddress(&pXpB, g_XpreB);
    cudaGetSymbolAddress(&pWFh, g_WihFh);
    cudaGetSymbolAddress(&pWBh, g_WihBh);
    cudaGetSymbolAddress(&pS1h, g_S1Wh);
    cudaGetSymbolAddress(&pBf,  g_biasf);
    cudaGetSymbolAddress(&pBb,  g_biasb);
    cudaGetSymbolAddress(&pY,   g_Y);
    cudaGetSymbolAddress(&pYh,  g_Yh);
    cudaGetSymbolAddress(&pCt,  g_Ct);
    cudaGetSymbolAddress(&pYqT, g_YqT);
    cudaGetSymbolAddress(&pMQT, g_MQT);
    cudaGetSymbolAddress(&pHm,  g_Hm);
    cudaGetSymbolAddress(&pAQ,  g_AQ);
    cudaGetSymbolAddress(&pAC,  g_AC);
    cudaGetSymbolAddress(&pBar, g_bar);
    __half* Xh  = (__half*)pXh;
    float*  XpF = (float*)pXpF;
    float*  XpB = (float*)pXpB;
    __half* WFh = (__half*)pWFh;
    __half* WBh = (__half*)pWBh;
    __half* S1h = (__half*)pS1h;
    float*  Bf  = (float*)pBf;
    float*  Bb  = (float*)pBb;
    float*  Y   = (float*)pY;
    __half* Yh  = (__half*)pYh;
    __half* Ct  = (__half*)pCt;
    __half* YqT = (__half*)pYqT;
    __half* MQT = (__half*)pMQT;
    float*  Hm  = (float*)pHm;
    __half* AQ  = (__half*)pAQ;
    __half* AC  = (__half*)pAC;
    int*    bars = (int*)pBar;

    cudaFuncSetAttribute(lstm_mma_kernel,
                         cudaFuncAttributeMaxDynamicSharedMemorySize,
                         LSTM_SMEM_BYTES);

    // 1. prep: bias fold, barrier reset, fp16 weight copies
    prep_kernel<<<1024, 256>>>(bihF, bhhF, bihB, bhhB, WihF, WihB, S1W,
                               Bf, Bb, WFh, WBh, S1h, bars);

    // 2. embedding gather -> fp16 X
    embed_kernel<<<12288, 256>>>(inQ, inC, inC2, (const float4*)emb, Xh);

    // 3. input GEMMs: Xpre = X @ Wih^T + (bih+bhh)
    run_g16(1, MX, G4, EE, Xh, EE, 0, WFh, EE, 0, XpF, G4, 0, Bf, 1);
    run_g16(1, MX, G4, EE, Xh, EE, 0, WBh, EE, 0, XpB, G4, 0, Bb, 1);

    // 4. recurrence (fp16 MMA, 96 resident CTAs, aggregate-barrier exchange)
    lstm_mma_kernel<<<96, 256, LSTM_SMEM_BYTES>>>(
        XpF, XpB, WhhF, WhhB,
        hidQ, celQ, hidC, celC, hidC2, celC2, Y, bars);

    // 4b. Y -> fp16 copy (exact)
    f2h_kernel<<<24576, 256>>>((const float4*)Y, (__half2*)Yh);

    // 5. Ct = tanh(Y_c @ S1_W^T + S1_b)  -> fp16
    run_g16(2, MBS, D2, D2, Yh + (size_t)1 * MBS * D2, D2, 0,
            S1h, D2, 0, Ct, D2, 0, S1b, 1);
    run_g16(2, MBS, D2, D2, Yh + (size_t)2 * MBS * D2, D2, 0,
            S1h, D2, 0, Ct + (size_t)MBS * D2, D2, 0, S1b, 1);

    // 5b. Yq^T
    {
        dim3 tg(D2 / 32, SQ / 32, BB), tb(32, 8);
        transpose_kernel<<<tg, tb>>>(Y, YqT);
    }

    // 6. attention for pairs (Q,C) and (Q,C2)
    for (int p = 0; p < 2; p++) {
        run_g16(0, SQ, SQ, D2,
                Yh, D2, (size_t)SQ * D2,
                Ct + (size_t)p * MBS * D2, D2, (size_t)SQ * D2,
                Hm, SQ, (size_t)SQ * SQ, nullptr, BB);
        row_softmax<<<2048, 256>>>(Hm, AQ);
        col_softmax<<<2048, 256>>>(Hm, AC);
        float* outMQ = out + (size_t)(2 * p) * OUTREG;
        float* outMC = out + (size_t)(2 * p + 1) * OUTREG;
        run_g16(0, SQ, D2, SQ,
                AQ, SQ, (size_t)SQ * SQ,
                YqT, SQ, (size_t)SQ * D2,
                outMQ, D2, (size_t)SQ * D2, nullptr, BB);
        {
            dim3 tg(D2 / 32, SQ / 32, BB), tb(32, 8);
            transpose_kernel<<<tg, tb>>>(outMQ, MQT);
        }
        run_g16(0, SQ, D2, SQ,
                AC, SQ, (size_t)SQ * SQ,
                MQT, SQ, (size_t)SQ * D2,
                outMC, D2, (size_t)SQ * D2, nullptr, BB);
    }
}